// round 7
// baseline (speedup 1.0000x reference)
#include <cuda_runtime.h>
#include <math.h>
#include <stdint.h>

#define B_  2
#define S_  2048
#define D_  768
#define H_  12
#define HD_ 64
#define L_  4
#define FF_ 3072
#define NC_ 16
#define W_  128

#define DD_   (D_*D_)            // 589824
#define DFF_  (D_*FF_)           // 2359296
#define WLS_  (6*DD_ + 2*DFF_)   // per-layer transposed-weight stride = 8257536

// ---------------- scratch (static device arrays; no allocation) ----------------
__device__ float g_h [B_*S_*D_];
__device__ float g_q [B_*S_*D_];
__device__ float g_k [B_*S_*D_];
__device__ float g_v [B_*S_*D_];
__device__ float g_kg[B_*S_*D_];
__device__ float g_vg[B_*S_*D_];
__device__ float g_a [B_*S_*D_];
__device__ float g_t [B_*S_*D_];
__device__ float g_ff[B_*S_*FF_];
__device__ float g_qg[B_*D_];
__device__ float g_wt[L_*WLS_];  // transposed weights [N][K], 132MB

// ---------------- helpers ----------------
__device__ __forceinline__ uint32_t smem_u32(const void* p) {
    return (uint32_t)__cvta_generic_to_shared(p);
}
__device__ __forceinline__ void cp16(uint32_t dst, const void* src) {
    asm volatile("cp.async.cg.shared.global [%0], [%1], 16;" :: "r"(dst), "l"(src));
}
__device__ __forceinline__ void cp_commit() { asm volatile("cp.async.commit_group;"); }
template <int N> __device__ __forceinline__ void cp_wait() {
    asm volatile("cp.async.wait_group %0;" :: "n"(N));
}
__device__ __forceinline__ uint32_t f2tf(float x) {
    uint32_t r;
    asm("cvt.rna.tf32.f32 %0, %1;" : "=r"(r) : "f"(x));
    return r;
}
__device__ __forceinline__ void ldsm4(uint32_t addr, unsigned* r) {
    asm volatile("ldmatrix.sync.aligned.m8n8.x4.shared.b16 {%0,%1,%2,%3}, [%4];"
        : "=r"(r[0]), "=r"(r[1]), "=r"(r[2]), "=r"(r[3]) : "r"(addr));
}

__device__ __forceinline__ void mma_tf32(float* c, const unsigned* a, const unsigned* b) {
    asm volatile(
        "mma.sync.aligned.m16n8k8.row.col.f32.tf32.tf32.f32 "
        "{%0,%1,%2,%3}, {%4,%5,%6,%7}, {%8,%9}, {%0,%1,%2,%3};"
        : "+f"(c[0]), "+f"(c[1]), "+f"(c[2]), "+f"(c[3])
        : "r"(a[0]), "r"(a[1]), "r"(a[2]), "r"(a[3]), "r"(b[0]), "r"(b[1]));
}

__device__ __forceinline__ void block_reduce2(float a, float b, float* out2) {
    __shared__ float r1[8], r2[8];
    int lane = threadIdx.x & 31, wid = threadIdx.x >> 5;
#pragma unroll
    for (int o = 16; o > 0; o >>= 1) {
        a += __shfl_down_sync(0xffffffffu, a, o);
        b += __shfl_down_sync(0xffffffffu, b, o);
    }
    if (lane == 0) { r1[wid] = a; r2[wid] = b; }
    __syncthreads();
    if (wid == 0) {
        int nw = blockDim.x >> 5;
        a = (lane < nw) ? r1[lane] : 0.f;
        b = (lane < nw) ? r2[lane] : 0.f;
#pragma unroll
        for (int o = 4; o > 0; o >>= 1) {
            a += __shfl_down_sync(0xffffffffu, a, o);
            b += __shfl_down_sync(0xffffffffu, b, o);
        }
        if (lane == 0) { out2[0] = a; out2[1] = b; }
    }
    __syncthreads();
}

// ---------------- weight transpose: src [K][N] -> dst [N][K] ----------------
__global__ void wtrans_kernel(const float* __restrict__ src, float* __restrict__ dst,
                              int K, int N, long sStride, long dStride) {
    __shared__ float t[32][33];
    const float* s = src + (long)blockIdx.z * sStride;
    float* d = dst + (long)blockIdx.z * dStride;
    int n0 = blockIdx.x * 32, k0 = blockIdx.y * 32;
    int tx = threadIdx.x, ty = threadIdx.y;     // 32 x 8
#pragma unroll
    for (int i = 0; i < 32; i += 8)
        t[ty + i][tx] = s[(size_t)(k0 + ty + i) * N + n0 + tx];
    __syncthreads();
#pragma unroll
    for (int i = 0; i < 32; i += 8)
        d[(size_t)(n0 + ty + i) * K + k0 + tx] = t[tx][ty + i];
}

// ---------------- tf32 GEMM: ldmatrix fragments, 3-stage cp.async ----------------
// C = act((A@Bt^T + bias) * alpha); A: MxK rm, Bt: NxK rm (pre-transposed weights).
// Block 128x128, 128 thr, 4 warps 2x2 (warp tile 64x64), K=16 per stage.
// Stage layout (A and B identical): 128 rows x 16 tf32, row stride 20 words
// (conflict-free LDSM: row starts cover all 32 banks in 16B groups).
template <int ACT>
__device__ __forceinline__ void gemm_core(
    const float* __restrict__ A, const float* __restrict__ Bt,
    const float* __restrict__ bias, float* __restrict__ C,
    int M, int N, int K, float alpha) {
    constexpr int STG = 128 * 20;            // words per stage
    constexpr int STGB = STG * 4;            // bytes per stage
    __shared__ uint32_t As[3 * STG];
    __shared__ uint32_t Bs[3 * STG];

    const int tid = threadIdx.x, lane = tid & 31, wid = tid >> 5;
    const int wm = (wid >> 1) * 64, wn = (wid & 1) * 64;
    const int g = lane >> 2, t = lane & 3;
    const int bm = blockIdx.y * 128, bn = blockIdx.x * 128;

    // cp.async slots: 4 chunks each for A and B (row = id>>2, chunk = id&3)
    uint32_t aDst[4], bDst[4];
    size_t aSrc[4], bSrc[4];
#pragma unroll
    for (int i = 0; i < 4; i++) {
        int id = tid + i * 128;
        int row = id >> 2, c = id & 3;
        aDst[i] = smem_u32(&As[row * 20 + c * 4]);
        bDst[i] = smem_u32(&Bs[row * 20 + c * 4]);
        aSrc[i] = (size_t)(bm + row) * K + c * 4;
        bSrc[i] = (size_t)(bn + row) * K + c * 4;
    }

    // ldmatrix lane addresses (lm = lane>>3 selects matrix, lr = lane&7 row)
    const int lm = lane >> 3, lr = lane & 7;
    const uint32_t aLd = smem_u32(As) + (((wm + (lm & 1) * 8 + lr) * 20 + (lm >> 1) * 4) << 2);
    const uint32_t bLd = smem_u32(Bs) + (((wn + (lm >> 1) * 8 + lr) * 20 + (lm & 1) * 4) << 2);

    float acc[4][8][4];
#pragma unroll
    for (int i = 0; i < 4; i++)
#pragma unroll
        for (int j = 0; j < 8; j++)
#pragma unroll
            for (int r = 0; r < 4; r++) acc[i][j][r] = 0.f;

    const int nk = K >> 4;

    auto issue = [&](int kt) {
        const int s = kt % 3;
        const int k0 = kt << 4;
#pragma unroll
        for (int i = 0; i < 4; i++) {
            cp16(aDst[i] + s * STGB, A + aSrc[i] + k0);
            cp16(bDst[i] + s * STGB, Bt + bSrc[i] + k0);
        }
        cp_commit();
    };

    issue(0);
    if (nk > 1) issue(1);

    for (int kt = 0; kt < nk; kt++) {
        if (kt + 1 == nk) cp_wait<0>(); else cp_wait<1>();
        __syncthreads();
        if (kt + 2 < nk) issue(kt + 2);

        const uint32_t sa = aLd + (kt % 3) * STGB;
        const uint32_t sb = bLd + (kt % 3) * STGB;
#pragma unroll
        for (int ks = 0; ks < 2; ks++) {
            const int kso = ks * 32;               // +8 words (bytes)
            unsigned af[4][4], bf[8][2];
#pragma unroll
            for (int mt = 0; mt < 4; mt++)
                ldsm4(sa + mt * 1280 + kso, af[mt]);   // 16 rows * 20 w * 4B = 1280
#pragma unroll
            for (int p = 0; p < 4; p++) {
                unsigned q[4];
                ldsm4(sb + p * 1280 + kso, q);
                bf[2*p][0] = q[0]; bf[2*p][1] = q[1];
                bf[2*p+1][0] = q[2]; bf[2*p+1][1] = q[3];
            }
#pragma unroll
            for (int mt = 0; mt < 4; mt++)
#pragma unroll
                for (int nt = 0; nt < 8; nt++)
                    mma_tf32(acc[mt][nt], af[mt], bf[nt]);
        }
    }

    // epilogue
#pragma unroll
    for (int mt = 0; mt < 4; mt++) {
#pragma unroll
        for (int nt = 0; nt < 8; nt++) {
            int r0 = bm + wm + mt * 16 + g;
            int c0 = bn + wn + nt * 8 + t * 2;
            float b0 = bias[c0], b1 = bias[c0 + 1];
            float v[4];
            v[0] = (acc[mt][nt][0] + b0) * alpha;
            v[1] = (acc[mt][nt][1] + b1) * alpha;
            v[2] = (acc[mt][nt][2] + b0) * alpha;
            v[3] = (acc[mt][nt][3] + b1) * alpha;
            if (ACT == 1) {
#pragma unroll
                for (int i = 0; i < 4; i++)
                    v[i] = 0.5f * v[i] * (1.f + erff(v[i] * 0.7071067811865476f));
            }
            *(float2*)(C + (size_t)r0 * N + c0)       = make_float2(v[0], v[1]);
            *(float2*)(C + (size_t)(r0 + 8) * N + c0) = make_float2(v[2], v[3]);
        }
    }
}

template <int ACT>
__global__ void __launch_bounds__(128, 2) tgemm_kernel(
    const float* __restrict__ A, const float* __restrict__ Bt,
    const float* __restrict__ bias, float* __restrict__ C,
    int M, int N, int K, float alpha) {
    gemm_core<ACT>(A, Bt, bias, C, M, N, K, alpha);
}

struct ProjParams {
    const float* W[5];
    const float* b[5];
    float*       o[5];
    float        alpha[5];
};

__global__ void __launch_bounds__(128, 2) proj_gemm_kernel(
    const float* __restrict__ A, ProjParams p, int M, int N, int K) {
    int z = blockIdx.z;
    gemm_core<0>(A, p.W[z], p.b[z], p.o[z], M, N, K, p.alpha[z]);
}

// ---------------- embedding + LN ----------------
__global__ void embed_ln_kernel(const int* __restrict__ src,
                                const float* __restrict__ etok,
                                const float* __restrict__ epos,
                                const float* __restrict__ gs,
                                const float* __restrict__ gb,
                                float* __restrict__ h) {
    int tok = blockIdx.x;
    int s   = tok & (S_ - 1);
    int tid = threadIdx.x;
    __shared__ float stat[2];
    size_t row = (size_t)src[tok] * D_;
    float vals[3]; float sum = 0.f, sq = 0.f;
#pragma unroll
    for (int i = 0; i < 3; i++) {
        int d = tid + i * 256;
        float v = etok[row + d] + epos[(size_t)s * D_ + d];
        vals[i] = v; sum += v; sq += v * v;
    }
    block_reduce2(sum, sq, stat);
    float mean = stat[0] * (1.f / D_);
    float var  = stat[1] * (1.f / D_) - mean * mean;
    float inv  = 1.f / sqrtf(var + 1e-5f);
#pragma unroll
    for (int i = 0; i < 3; i++) {
        int d = tid + i * 256;
        h[(size_t)tok * D_ + d] = (vals[i] - mean) * inv * gs[d] + gb[d];
    }
}

// ---------------- residual add + LN (in place on h) ----------------
__global__ void add_ln_kernel(float* __restrict__ h, const float* __restrict__ x,
                              const float* __restrict__ sc, const float* __restrict__ bi) {
    int tok = blockIdx.x;
    int tid = threadIdx.x;
    __shared__ float stat[2];
    float* hp = h + (size_t)tok * D_;
    const float* xp = x + (size_t)tok * D_;
    float vals[3]; float sum = 0.f, sq = 0.f;
#pragma unroll
    for (int i = 0; i < 3; i++) {
        int d = tid + i * 256;
        float v = hp[d] + xp[d];
        vals[i] = v; sum += v; sq += v * v;
    }
    block_reduce2(sum, sq, stat);
    float mean = stat[0] * (1.f / D_);
    float var  = stat[1] * (1.f / D_) - mean * mean;
    float inv  = 1.f / sqrtf(var + 1e-5f);
#pragma unroll
    for (int i = 0; i < 3; i++) {
        int d = tid + i * 256;
        hp[d] = (vals[i] - mean) * inv * sc[d] + bi[d];
    }
}

// ---------------- qg = (h[:,0,:] @ Wqg + bqg) / 8 ----------------
__global__ void qg_kernel(const float* __restrict__ h, const float* __restrict__ Wm,
                          const float* __restrict__ bias, float* __restrict__ qg) {
    int b = blockIdx.x;
    int j = blockIdx.y * 256 + threadIdx.x;
    __shared__ float hs[D_];
    for (int i = threadIdx.x; i < D_; i += 256) hs[i] = h[(size_t)b * S_ * D_ + i];
    __syncthreads();
    float s = 0.f;
    for (int kk = 0; kk < D_; kk++) s = fmaf(hs[kk], Wm[(size_t)kk * D_ + j], s);
    qg[b * D_ + j] = (s + bias[j]) * 0.125f;
}

// ---------------- sliding-window + global-key attention (tensor-core flash) -----
__global__ void __launch_bounds__(256) attn_kernel(
    const float* __restrict__ q, const float* __restrict__ k, const float* __restrict__ v,
    const int* __restrict__ mask, float* __restrict__ out) {
    const int c = blockIdx.x, hh = blockIdx.y, b = blockIdx.z;
    const int tid = threadIdx.x, lane = tid & 31, wid = tid >> 5;
    const int g = lane >> 2, t = lane & 3;
    const int wq = wid * 16;
    __shared__ float Ks[64 * 68];
    __shared__ float Vs[64 * 72];
    __shared__ float k0s[64], v0s[64];
    __shared__ int vld[64];

    const size_t hb = (size_t)b * S_ * D_ + hh * HD_;

    if (tid < 64) { k0s[tid] = k[hb + tid]; v0s[tid] = v[hb + tid]; }

    uint32_t Qf[8][4];
    {
        const float* qr0 = q + hb + (size_t)(c * W_ + wq + g) * D_;
        const float* qr1 = qr0 + 8 * D_;
#pragma unroll
        for (int kk = 0; kk < 8; kk++) {
            Qf[kk][0] = f2tf(qr0[kk * 8 + t]);
            Qf[kk][1] = f2tf(qr1[kk * 8 + t]);
            Qf[kk][2] = f2tf(qr0[kk * 8 + t + 4]);
            Qf[kk][3] = f2tf(qr1[kk * 8 + t + 4]);
        }
    }
    __syncthreads();

    float p0 = 0.f, p1 = 0.f;
#pragma unroll
    for (int kk = 0; kk < 8; kk++) {
        p0 += __uint_as_float(Qf[kk][0]) * k0s[kk*8 + t] + __uint_as_float(Qf[kk][2]) * k0s[kk*8 + t + 4];
        p1 += __uint_as_float(Qf[kk][1]) * k0s[kk*8 + t] + __uint_as_float(Qf[kk][3]) * k0s[kk*8 + t + 4];
    }
    p0 += __shfl_xor_sync(0xffffffffu, p0, 1); p0 += __shfl_xor_sync(0xffffffffu, p0, 2);
    p1 += __shfl_xor_sync(0xffffffffu, p1, 1); p1 += __shfl_xor_sync(0xffffffffu, p1, 2);

    const bool m0set = mask[(size_t)b * S_] != 0;
    float m0 = m0set ? p0 : -1e30f;
    float m1 = m0set ? p1 : -1e30f;
    float l0 = m0set ? 1.f : 0.f;
    float l1 = l0;
    float acc[8][4];
#pragma unroll
    for (int nt = 0; nt < 8; nt++) {
        float va = m0set ? v0s[nt*8 + 2*t]     : 0.f;
        float vb = m0set ? v0s[nt*8 + 2*t + 1] : 0.f;
        acc[nt][0] = va; acc[nt][1] = vb; acc[nt][2] = va; acc[nt][3] = vb;
    }

    const int base = c * W_ - W_;
    const int q0r = wq + g, q1r = q0r + 8;
    const uint32_t* Ku = (const uint32_t*)Ks;
    const uint32_t* Vu = (const uint32_t*)Vs;

    for (int tile = 0; tile < 6; tile++) {
        __syncthreads();
#pragma unroll
        for (int e = 0; e < 4; e++) {
            int id = tid + e * 256;
            int r = id >> 4, c4 = (id & 15) * 4;
            int p = base + tile * 64 + r;
            float4 kv = make_float4(0.f,0.f,0.f,0.f), vv = kv;
            if (p >= 0 && p < S_) {
                size_t off = hb + (size_t)p * D_ + c4;
                kv = *(const float4*)(k + off);
                vv = *(const float4*)(v + off);
            }
            uint32_t* kd = (uint32_t*)&Ks[r * 68 + c4];
            kd[0] = f2tf(kv.x); kd[1] = f2tf(kv.y); kd[2] = f2tf(kv.z); kd[3] = f2tf(kv.w);
            uint32_t* vd = (uint32_t*)&Vs[r * 72 + c4];
            vd[0] = f2tf(vv.x); vd[1] = f2tf(vv.y); vd[2] = f2tf(vv.z); vd[3] = f2tf(vv.w);
        }
        if (tid < 64) {
            int p = base + tile * 64 + tid;
            vld[tid] = (p >= 0 && p < S_) ? (mask[(size_t)b * S_ + p] != 0) : 0;
        }
        __syncthreads();

        float sc[8][4];
#pragma unroll
        for (int nt = 0; nt < 8; nt++) { sc[nt][0]=0.f; sc[nt][1]=0.f; sc[nt][2]=0.f; sc[nt][3]=0.f; }
#pragma unroll
        for (int kk = 0; kk < 8; kk++) {
#pragma unroll
            for (int nt = 0; nt < 8; nt++) {
                unsigned bf[2];
                bf[0] = Ku[(nt*8 + g) * 68 + kk*8 + t];
                bf[1] = Ku[(nt*8 + g) * 68 + kk*8 + t + 4];
                mma_tf32(sc[nt], Qf[kk], bf);
            }
        }

        float tm0 = -1e30f, tm1 = -1e30f;
#pragma unroll
        for (int nt = 0; nt < 8; nt++) {
            int j0 = tile*64 + nt*8 + 2*t, j1 = j0 + 1;
            bool ok00 = (j0 >= q0r) && (j0 <= q0r + 2*W_) && vld[nt*8 + 2*t];
            bool ok01 = (j1 >= q0r) && (j1 <= q0r + 2*W_) && vld[nt*8 + 2*t + 1];
            bool ok10 = (j0 >= q1r) && (j0 <= q1r + 2*W_) && vld[nt*8 + 2*t];
            bool ok11 = (j1 >= q1r) && (j1 <= q1r + 2*W_) && vld[nt*8 + 2*t + 1];
            sc[nt][0] = ok00 ? sc[nt][0] : -1e30f;
            sc[nt][1] = ok01 ? sc[nt][1] : -1e30f;
            sc[nt][2] = ok10 ? sc[nt][2] : -1e30f;
            sc[nt][3] = ok11 ? sc[nt][3] : -1e30f;
            tm0 = fmaxf(tm0, fmaxf(sc[nt][0], sc[nt][1]));
            tm1 = fmaxf(tm1, fmaxf(sc[nt][2], sc[nt][3]));
        }
        tm0 = fmaxf(tm0, __shfl_xor_sync(0xffffffffu, tm0, 1));
        tm0 = fmaxf(tm0, __shfl_xor_sync(0xffffffffu, tm0, 2));
        tm1 = fmaxf(tm1, __shfl_xor_sync(0xffffffffu, tm1, 1));
        tm1 = fmaxf(tm1, __shfl_xor_sync(0xffffffffu, tm1, 2));

        float nm0 = fmaxf(m0, tm0), nm1 = fmaxf(m1, tm1);
        float cr0 = __expf(m0 - nm0), cr1 = __expf(m1 - nm1);
        m0 = nm0; m1 = nm1; l0 *= cr0; l1 *= cr1;

        float ps0 = 0.f, ps1 = 0.f;
#pragma unroll
        for (int nt = 0; nt < 8; nt++) {
            sc[nt][0] = (sc[nt][0] > -1e29f) ? __expf(sc[nt][0] - m0) : 0.f;
            sc[nt][1] = (sc[nt][1] > -1e29f) ? __expf(sc[nt][1] - m0) : 0.f;
            sc[nt][2] = (sc[nt][2] > -1e29f) ? __expf(sc[nt][2] - m1) : 0.f;
            sc[nt][3] = (sc[nt][3] > -1e29f) ? __expf(sc[nt][3] - m1) : 0.f;
            ps0 += sc[nt][0] + sc[nt][1];
            ps1 += sc[nt][2] + sc[nt][3];
            acc[nt][0] *= cr0; acc[nt][1] *= cr0; acc[nt][2] *= cr1; acc[nt][3] *= cr1;
        }
        ps0 += __shfl_xor_sync(0xffffffffu, ps0, 1); ps0 += __shfl_xor_sync(0xffffffffu, ps0, 2);
        ps1 += __shfl_xor_sync(0xffffffffu, ps1, 1); ps1 += __shfl_xor_sync(0xffffffffu, ps1, 2);
        l0 += ps0; l1 += ps1;

        const int src0 = (lane & ~3) | (t >> 1);
        const int src1 = src0 + 2;
        const bool odd = t & 1;
#pragma unroll
        for (int kk = 0; kk < 8; kk++) {
            float x0 = __shfl_sync(0xffffffffu, sc[kk][0], src0);
            float x1 = __shfl_sync(0xffffffffu, sc[kk][1], src0);
            float x2 = __shfl_sync(0xffffffffu, sc[kk][2], src0);
            float x3 = __shfl_sync(0xffffffffu, sc[kk][3], src0);
            float y0 = __shfl_sync(0xffffffffu, sc[kk][0], src1);
            float y1 = __shfl_sync(0xffffffffu, sc[kk][1], src1);
            float y2 = __shfl_sync(0xffffffffu, sc[kk][2], src1);
            float y3 = __shfl_sync(0xffffffffu, sc[kk][3], src1);
            unsigned af[4];
            af[0] = f2tf(odd ? x1 : x0);
            af[1] = f2tf(odd ? x3 : x2);
            af[2] = f2tf(odd ? y1 : y0);
            af[3] = f2tf(odd ? y3 : y2);
#pragma unroll
            for (int nt = 0; nt < 8; nt++) {
                unsigned bf[2];
                bf[0] = Vu[(kk*8 + t) * 72 + nt*8 + g];
                bf[1] = Vu[(kk*8 + t + 4) * 72 + nt*8 + g];
                mma_tf32(acc[nt], af, bf);
            }
        }
    }

    float inv0 = 1.f / l0, inv1 = 1.f / l1;
    float* or0 = out + hb + (size_t)(c * W_ + wq + g) * D_;
    float* or1 = or0 + 8 * D_;
#pragma unroll
    for (int nt = 0; nt < 8; nt++) {
        *(float2*)(or0 + nt*8 + 2*t) = make_float2(acc[nt][0] * inv0, acc[nt][1] * inv0);
        *(float2*)(or1 + nt*8 + 2*t) = make_float2(acc[nt][2] * inv1, acc[nt][3] * inv1);
    }
}

// ---------------- global-token attention -> overwrite out row 0 ----------------
__global__ void __launch_bounds__(256) gattn_kernel(
    const float* __restrict__ qg, const float* __restrict__ kg,
    const float* __restrict__ vg, const int* __restrict__ mask,
    float* __restrict__ out) {
    const int hh = blockIdx.x, b = blockIdx.y;
    const int tid = threadIdx.x;
    __shared__ float sc[S_];
    __shared__ float qs[HD_];
    __shared__ float r1[8];
    __shared__ float stat[2];
    __shared__ float accb[4][HD_];
    if (tid < HD_) qs[tid] = qg[b * D_ + hh * HD_ + tid];
    __syncthreads();
    float lmax = -3.4e38f;
    for (int s = tid; s < S_; s += 256) {
        const float4* kr = (const float4*)(kg + ((size_t)b * S_ + s) * D_ + hh * HD_);
        float dot = 0.f;
#pragma unroll
        for (int i = 0; i < 16; i++) {
            float4 k4 = kr[i];
            dot = fmaf(qs[i*4], k4.x, dot);   dot = fmaf(qs[i*4+1], k4.y, dot);
            dot = fmaf(qs[i*4+2], k4.z, dot); dot = fmaf(qs[i*4+3], k4.w, dot);
        }
        if (mask[(size_t)b * S_ + s] == 0) dot = -1e9f;
        sc[s] = dot;
        lmax = fmaxf(lmax, dot);
    }
    {
        int lane = tid & 31, wid = tid >> 5;
#pragma unroll
        for (int o = 16; o > 0; o >>= 1) lmax = fmaxf(lmax, __shfl_down_sync(0xffffffffu, lmax, o));
        if (lane == 0) r1[wid] = lmax;
        __syncthreads();
        if (tid == 0) {
            float m2 = r1[0];
            for (int i = 1; i < 8; i++) m2 = fmaxf(m2, r1[i]);
            stat[0] = m2;
        }
        __syncthreads();
    }
    float gmax = stat[0];
    float lsum = 0.f;
    for (int s = tid; s < S_; s += 256) {
        float e = __expf(sc[s] - gmax);
        sc[s] = e;
        lsum += e;
    }
    {
        int lane = tid & 31, wid = tid >> 5;
#pragma unroll
        for (int o = 16; o > 0; o >>= 1) lsum += __shfl_down_sync(0xffffffffu, lsum, o);
        if (lane == 0) r1[wid] = lsum;
        __syncthreads();
        if (tid == 0) {
            float s2 = 0.f;
            for (int i = 0; i < 8; i++) s2 += r1[i];
            stat[1] = s2;
        }
        __syncthreads();
    }
    float inv = 1.f / stat[1];
    int d = tid & 63, part = tid >> 6;
    float a = 0.f;
    for (int s = part; s < S_; s += 4)
        a = fmaf(sc[s], vg[((size_t)b * S_ + s) * D_ + hh * HD_ + d], a);
    accb[part][d] = a;
    __syncthreads();
    if (tid < HD_)
        out[(size_t)b * S_ * D_ + hh * HD_ + tid] =
            (accb[0][tid] + accb[1][tid] + accb[2][tid] + accb[3][tid]) * inv;
}

// ---------------- classifier head ----------------
__global__ void cls_kernel(const float* __restrict__ h, const float* __restrict__ Wcls,
                           const float* __restrict__ bcls, const int* __restrict__ mask,
                           float* __restrict__ out) {
    int w = threadIdx.x >> 5, lane = threadIdx.x & 31;
    int b = w & 1, j = w >> 1;
    float s = 0.f;
    for (int kk = lane; kk < D_; kk += 32)
        s = fmaf(h[(size_t)b * S_ * D_ + kk], Wcls[kk * 3 + j], s);
#pragma unroll
    for (int o = 16; o > 0; o >>= 1) s += __shfl_down_sync(0xffffffffu, s, o);
    if (lane == 0) out[j * 2 + b] = 1.f / (1.f + expf(-(s + bcls[j])));
    if (threadIdx.x < 2) out[6 + threadIdx.x] = (float)mask[(size_t)threadIdx.x * S_];
}

// ---------------- launch ----------------
extern "C" void kernel_launch(void* const* d_in, const int* in_sizes, int n_in,
                              void* d_out, int out_size) {
    const int*   src  = (const int*)d_in[0];
    const int*   mask = (const int*)d_in[1];
    const float* etok = (const float*)d_in[3];
    const float* epos = (const float*)d_in[4];
    const float* elns = (const float*)d_in[5];
    const float* elnb = (const float*)d_in[6];
    const float* Wq   = (const float*)d_in[7];   const float* bq_p  = (const float*)d_in[8];
    const float* Wk   = (const float*)d_in[9];   const float* bk_p  = (const float*)d_in[10];
    const float* Wv   = (const float*)d_in[11];  const float* bv_p  = (const float*)d_in[12];
    const float* Wo   = (const float*)d_in[13];  const float* bo_p  = (const float*)d_in[14];
    const float* Wqg  = (const float*)d_in[15];  const float* bqg_p = (const float*)d_in[16];
    const float* Wkg  = (const float*)d_in[17];  const float* bkg_p = (const float*)d_in[18];
    const float* Wvg  = (const float*)d_in[19];  const float* bvg_p = (const float*)d_in[20];
    const float* ln1s = (const float*)d_in[21];  const float* ln1b  = (const float*)d_in[22];
    const float* W1   = (const float*)d_in[23];  const float* b1_p  = (const float*)d_in[24];
    const float* W2   = (const float*)d_in[25];  const float* b2_p  = (const float*)d_in[26];
    const float* ln2s = (const float*)d_in[27];  const float* ln2b  = (const float*)d_in[28];
    const float* Wcls = (const float*)d_in[29];  const float* bcls  = (const float*)d_in[30];
    float* out = (float*)d_out;

    float *ph, *pq, *pk, *pv, *pkg, *pvg, *pa, *pt, *pf, *pqg, *pwt;
    cudaGetSymbolAddress((void**)&ph,  g_h);
    cudaGetSymbolAddress((void**)&pq,  g_q);
    cudaGetSymbolAddress((void**)&pk,  g_k);
    cudaGetSymbolAddress((void**)&pv,  g_v);
    cudaGetSymbolAddress((void**)&pkg, g_kg);
    cudaGetSymbolAddress((void**)&pvg, g_vg);
    cudaGetSymbolAddress((void**)&pa,  g_a);
    cudaGetSymbolAddress((void**)&pt,  g_t);
    cudaGetSymbolAddress((void**)&pf,  g_ff);
    cudaGetSymbolAddress((void**)&pqg, g_qg);
    cudaGetSymbolAddress((void**)&pwt, g_wt);

    const int M = B_ * S_;   // 4096

    // transpose all GEMM weights to [N][K] (per replay; ~50us)
    {
        dim3 bt(32, 8);
        dim3 gDD(D_ / 32, D_ / 32, L_);
        wtrans_kernel<<<gDD, bt>>>(Wq,  pwt + 0*DD_, D_, D_, DD_, WLS_);
        wtrans_kernel<<<gDD, bt>>>(Wk,  pwt + 1*DD_, D_, D_, DD_, WLS_);
        wtrans_kernel<<<gDD, bt>>>(Wv,  pwt + 2*DD_, D_, D_, DD_, WLS_);
        wtrans_kernel<<<gDD, bt>>>(Wkg, pwt + 3*DD_, D_, D_, DD_, WLS_);
        wtrans_kernel<<<gDD, bt>>>(Wvg, pwt + 4*DD_, D_, D_, DD_, WLS_);
        wtrans_kernel<<<gDD, bt>>>(Wo,  pwt + 5*DD_, D_, D_, DD_, WLS_);
        wtrans_kernel<<<dim3(FF_ / 32, D_ / 32, L_), bt>>>(W1, pwt + 6*DD_, D_, FF_, DFF_, WLS_);
        wtrans_kernel<<<dim3(D_ / 32, FF_ / 32, L_), bt>>>(W2, pwt + 6*DD_ + DFF_, FF_, D_, DFF_, WLS_);
    }

    embed_ln_kernel<<<M, 256>>>(src, etok, epos, elns, elnb, ph);

    for (int l = 0; l < L_; l++) {
        float* wl = pwt + (size_t)l * WLS_;
        size_t bof = (size_t)l * D_;

        ProjParams pp;
        pp.W[0] = wl + 0*DD_; pp.b[0] = bq_p  + bof; pp.o[0] = pq;  pp.alpha[0] = 0.125f;
        pp.W[1] = wl + 1*DD_; pp.b[1] = bk_p  + bof; pp.o[1] = pk;  pp.alpha[1] = 1.f;
        pp.W[2] = wl + 2*DD_; pp.b[2] = bv_p  + bof; pp.o[2] = pv;  pp.alpha[2] = 1.f;
        pp.W[3] = wl + 3*DD_; pp.b[3] = bkg_p + bof; pp.o[3] = pkg; pp.alpha[3] = 1.f;
        pp.W[4] = wl + 4*DD_; pp.b[4] = bvg_p + bof; pp.o[4] = pvg; pp.alpha[4] = 1.f;
        proj_gemm_kernel<<<dim3(D_ / 128, M / 128, 5), 128>>>(ph, pp, M, D_, D_);

        qg_kernel<<<dim3(B_, 3), 256>>>(ph, Wqg + (size_t)l * DD_, bqg_p + bof, pqg);
        attn_kernel<<<dim3(NC_, H_, B_), 256>>>(pq, pk, pv, mask, pa);
        gattn_kernel<<<dim3(H_, B_), 256>>>(pqg, pkg, pvg, mask, pa);

        tgemm_kernel<0><<<dim3(D_ / 128, M / 128), 128>>>(pa, wl + 5*DD_, bo_p + bof, pt, M, D_, D_, 1.f);
        add_ln_kernel<<<M, 256>>>(ph, pt, ln1s + bof, ln1b + bof);
        tgemm_kernel<1><<<dim3(FF_ / 128, M / 128), 128>>>(ph, wl + 6*DD_,
                                                           b1_p + (size_t)l * FF_, pf, M, FF_, D_, 1.f);
        tgemm_kernel<0><<<dim3(D_ / 128, M / 128), 128>>>(pf, wl + 6*DD_ + DFF_,
                                                          b2_p + bof, pt, M, D_, FF_, 1.f);
        add_ln_kernel<<<M, 256>>>(ph, pt, ln2s + bof, ln2b + bof);
    }

    cls_kernel<<<1, 192>>>(ph, Wcls, bcls, mask, out);
}

// round 10
// speedup vs baseline: 1.6856x; 1.6856x over previous
#include <cuda_runtime.h>
#include <math.h>
#include <stdint.h>

#define B_  2
#define S_  2048
#define D_  768
#define H_  12
#define HD_ 64
#define L_  4
#define FF_ 3072
#define NC_ 16
#define W_  128

// ---------------- scratch (static device arrays; no allocation) ----------------
__device__ float g_h [B_*S_*D_];
__device__ float g_q [B_*S_*D_];
__device__ float g_k [B_*S_*D_];
__device__ float g_v [B_*S_*D_];
__device__ float g_kg[B_*S_*D_];
__device__ float g_vg[B_*S_*D_];
__device__ float g_a [B_*S_*D_];
__device__ float g_t [B_*S_*D_];
__device__ float g_ff[B_*S_*FF_];
__device__ float g_qg[B_*D_];

// ---------------- helpers ----------------
__device__ __forceinline__ uint32_t smem_u32(const void* p) {
    return (uint32_t)__cvta_generic_to_shared(p);
}
__device__ __forceinline__ void cp16(uint32_t dst, const void* src) {
    asm volatile("cp.async.cg.shared.global [%0], [%1], 16;" :: "r"(dst), "l"(src));
}
__device__ __forceinline__ void cp_commit() { asm volatile("cp.async.commit_group;"); }
template <int N> __device__ __forceinline__ void cp_wait() {
    asm volatile("cp.async.wait_group %0;" :: "n"(N));
}
__device__ __forceinline__ uint32_t f2tf(float x) {
    uint32_t r;
    asm("cvt.rna.tf32.f32 %0, %1;" : "=r"(r) : "f"(x));
    return r;
}
__device__ __forceinline__ void ldsm4(uint32_t addr, unsigned* r) {
    asm volatile("ldmatrix.sync.aligned.m8n8.x4.shared.b16 {%0,%1,%2,%3}, [%4];"
        : "=r"(r[0]), "=r"(r[1]), "=r"(r[2]), "=r"(r[3]) : "r"(addr));
}

__device__ __forceinline__ void mma_tf32(float* c, const unsigned* a, const unsigned* b) {
    asm volatile(
        "mma.sync.aligned.m16n8k8.row.col.f32.tf32.tf32.f32 "
        "{%0,%1,%2,%3}, {%4,%5,%6,%7}, {%8,%9}, {%0,%1,%2,%3};"
        : "+f"(c[0]), "+f"(c[1]), "+f"(c[2]), "+f"(c[3])
        : "r"(a[0]), "r"(a[1]), "r"(a[2]), "r"(a[3]), "r"(b[0]), "r"(b[1]));
}

__device__ __forceinline__ void block_reduce2(float a, float b, float* out2) {
    __shared__ float r1[8], r2[8];
    int lane = threadIdx.x & 31, wid = threadIdx.x >> 5;
#pragma unroll
    for (int o = 16; o > 0; o >>= 1) {
        a += __shfl_down_sync(0xffffffffu, a, o);
        b += __shfl_down_sync(0xffffffffu, b, o);
    }
    if (lane == 0) { r1[wid] = a; r2[wid] = b; }
    __syncthreads();
    if (wid == 0) {
        int nw = blockDim.x >> 5;
        a = (lane < nw) ? r1[lane] : 0.f;
        b = (lane < nw) ? r2[lane] : 0.f;
#pragma unroll
        for (int o = 4; o > 0; o >>= 1) {
            a += __shfl_down_sync(0xffffffffu, a, o);
            b += __shfl_down_sync(0xffffffffu, b, o);
        }
        if (lane == 0) { out2[0] = a; out2[1] = b; }
    }
    __syncthreads();
}

// ---------------- tf32 GEMM: A via ldmatrix, B via scalar LDS (round-5 path) ----
// C = act((A@B + bias) * alpha); A: MxK rm, B: KxN rm (ORIGINAL weights).
// Block 128x128x16, 128 thr, 4 warps 2x2 (warp tile 64x64), 3-stage cp.async.
// A stage: 128 rows x 16 words (64B rows), chunk swizzle c^((row>>1)&3):
//   conflict-free for both cp.async stores and ldmatrix reads.
// B stage: 16 rows x 136 words (round-5 proven: streaming global, CF reads).
template <int ACT>
__device__ __forceinline__ void gemm_core(
    const float* __restrict__ A, const float* __restrict__ Bm,
    const float* __restrict__ bias, float* __restrict__ C,
    int M, int N, int K, float alpha) {
    constexpr int ASTG = 128 * 16;           // words per A stage
    constexpr int BSTG = 16 * 136;           // words per B stage
    __shared__ uint32_t As[3 * ASTG];
    __shared__ uint32_t Bs[3 * BSTG];

    const int tid = threadIdx.x, lane = tid & 31, wid = tid >> 5;
    const int wm = (wid >> 1) * 64, wn = (wid & 1) * 64;
    const int g = lane >> 2, t = lane & 3;
    const int bm = blockIdx.y * 128, bn = blockIdx.x * 128;

    // cp.async slots: A 4 chunks (row=f>>2, c=f&3, swizzled), B 4 chunks (row=f>>5, c=f&31)
    uint32_t aDst[4], bDst[4];
    size_t aSrc[4];
    int brow[4], bcol[4];
#pragma unroll
    for (int i = 0; i < 4; i++) {
        int f = tid + i * 128;
        int ar = f >> 2, ac = f & 3;
        aDst[i] = smem_u32(As) + (ar << 6) + ((ac ^ ((ar >> 1) & 3)) << 4);
        aSrc[i] = (size_t)(bm + ar) * K + ac * 4;
        brow[i] = f >> 5;
        bcol[i] = bn + (f & 31) * 4;
        bDst[i] = smem_u32(Bs) + (brow[i] * 136 + (f & 31) * 4) * 4;
    }

    // ldmatrix A lane address: matrix lm=lane>>3 (row +8 via lm&1, chunk +1 via lm>>1)
    const int lm = lane >> 3, lr = lane & 7;
    const uint32_t aLd = smem_u32(As) + ((wm + (lm & 1) * 8 + lr) << 6);
    const int xorT = (lr >> 1) & 3;
    const int csel = lm >> 1;

    float acc[4][8][4];
#pragma unroll
    for (int i = 0; i < 4; i++)
#pragma unroll
        for (int j = 0; j < 8; j++)
#pragma unroll
            for (int r = 0; r < 4; r++) acc[i][j][r] = 0.f;

    const int nk = K >> 4;

    auto issue = [&](int kt) {
        const int s = kt % 3;
        const int k0 = kt << 4;
#pragma unroll
        for (int i = 0; i < 4; i++) {
            cp16(aDst[i] + s * (ASTG * 4), A + aSrc[i] + k0);
            cp16(bDst[i] + s * (BSTG * 4), Bm + (size_t)(k0 + brow[i]) * N + bcol[i]);
        }
        cp_commit();
    };

    issue(0);
    if (nk > 1) issue(1);

    for (int kt = 0; kt < nk; kt++) {
        if (kt + 1 == nk) cp_wait<0>(); else cp_wait<1>();
        __syncthreads();
        if (kt + 2 < nk) issue(kt + 2);

        const uint32_t sa = aLd + (kt % 3) * (ASTG * 4);
        const uint32_t* sB = &Bs[(kt % 3) * BSTG];
#pragma unroll
        for (int ks = 0; ks < 2; ks++) {
            const int kb = ks * 8;
            const uint32_t aoff = (uint32_t)(((2 * ks + csel) ^ xorT) << 4);
            unsigned af[4][4], bf[8][2];
#pragma unroll
            for (int mt = 0; mt < 4; mt++)
                ldsm4(sa + mt * 1024 + aoff, af[mt]);   // 16 rows * 64B = 1024
#pragma unroll
            for (int nt = 0; nt < 8; nt++) {
                int cc = wn + nt * 8 + g;
                bf[nt][0] = sB[(kb + t) * 136 + cc];
                bf[nt][1] = sB[(kb + t + 4) * 136 + cc];
            }
#pragma unroll
            for (int mt = 0; mt < 4; mt++)
#pragma unroll
                for (int nt = 0; nt < 8; nt++)
                    mma_tf32(acc[mt][nt], af[mt], bf[nt]);
        }
        __syncthreads();
    }

    // epilogue
#pragma unroll
    for (int mt = 0; mt < 4; mt++) {
#pragma unroll
        for (int nt = 0; nt < 8; nt++) {
            int r0 = bm + wm + mt * 16 + g;
            int c0 = bn + wn + nt * 8 + t * 2;
            float b0 = bias[c0], b1 = bias[c0 + 1];
            float v[4];
            v[0] = (acc[mt][nt][0] + b0) * alpha;
            v[1] = (acc[mt][nt][1] + b1) * alpha;
            v[2] = (acc[mt][nt][2] + b0) * alpha;
            v[3] = (acc[mt][nt][3] + b1) * alpha;
            if (ACT == 1) {
#pragma unroll
                for (int i = 0; i < 4; i++)
                    v[i] = 0.5f * v[i] * (1.f + erff(v[i] * 0.7071067811865476f));
            }
            *(float2*)(C + (size_t)r0 * N + c0)       = make_float2(v[0], v[1]);
            *(float2*)(C + (size_t)(r0 + 8) * N + c0) = make_float2(v[2], v[3]);
        }
    }
}

template <int ACT>
__global__ void __launch_bounds__(128, 2) tgemm_kernel(
    const float* __restrict__ A, const float* __restrict__ Bm,
    const float* __restrict__ bias, float* __restrict__ C,
    int M, int N, int K, float alpha) {
    gemm_core<ACT>(A, Bm, bias, C, M, N, K, alpha);
}

struct ProjParams {
    const float* W[5];
    const float* b[5];
    float*       o[5];
    float        alpha[5];
};

__global__ void __launch_bounds__(128, 2) proj_gemm_kernel(
    const float* __restrict__ A, ProjParams p, int M, int N, int K) {
    int z = blockIdx.z;
    gemm_core<0>(A, p.W[z], p.b[z], p.o[z], M, N, K, p.alpha[z]);
}

// ---------------- embedding + LN ----------------
__global__ void embed_ln_kernel(const int* __restrict__ src,
                                const float* __restrict__ etok,
                                const float* __restrict__ epos,
                                const float* __restrict__ gs,
                                const float* __restrict__ gb,
                                float* __restrict__ h) {
    int tok = blockIdx.x;
    int s   = tok & (S_ - 1);
    int tid = threadIdx.x;
    __shared__ float stat[2];
    size_t row = (size_t)src[tok] * D_;
    float vals[3]; float sum = 0.f, sq = 0.f;
#pragma unroll
    for (int i = 0; i < 3; i++) {
        int d = tid + i * 256;
        float v = etok[row + d] + epos[(size_t)s * D_ + d];
        vals[i] = v; sum += v; sq += v * v;
    }
    block_reduce2(sum, sq, stat);
    float mean = stat[0] * (1.f / D_);
    float var  = stat[1] * (1.f / D_) - mean * mean;
    float inv  = 1.f / sqrtf(var + 1e-5f);
#pragma unroll
    for (int i = 0; i < 3; i++) {
        int d = tid + i * 256;
        h[(size_t)tok * D_ + d] = (vals[i] - mean) * inv * gs[d] + gb[d];
    }
}

// ---------------- residual add + LN (in place on h) ----------------
__global__ void add_ln_kernel(float* __restrict__ h, const float* __restrict__ x,
                              const float* __restrict__ sc, const float* __restrict__ bi) {
    int tok = blockIdx.x;
    int tid = threadIdx.x;
    __shared__ float stat[2];
    float* hp = h + (size_t)tok * D_;
    const float* xp = x + (size_t)tok * D_;
    float vals[3]; float sum = 0.f, sq = 0.f;
#pragma unroll
    for (int i = 0; i < 3; i++) {
        int d = tid + i * 256;
        float v = hp[d] + xp[d];
        vals[i] = v; sum += v; sq += v * v;
    }
    block_reduce2(sum, sq, stat);
    float mean = stat[0] * (1.f / D_);
    float var  = stat[1] * (1.f / D_) - mean * mean;
    float inv  = 1.f / sqrtf(var + 1e-5f);
#pragma unroll
    for (int i = 0; i < 3; i++) {
        int d = tid + i * 256;
        hp[d] = (vals[i] - mean) * inv * sc[d] + bi[d];
    }
}

// ---------------- qg = (h[:,0,:] @ Wqg + bqg) / 8 ----------------
__global__ void qg_kernel(const float* __restrict__ h, const float* __restrict__ Wm,
                          const float* __restrict__ bias, float* __restrict__ qg) {
    int b = blockIdx.x;
    int j = blockIdx.y * 256 + threadIdx.x;
    __shared__ float hs[D_];
    for (int i = threadIdx.x; i < D_; i += 256) hs[i] = h[(size_t)b * S_ * D_ + i];
    __syncthreads();
    float s = 0.f;
    for (int kk = 0; kk < D_; kk++) s = fmaf(hs[kk], Wm[(size_t)kk * D_ + j], s);
    qg[b * D_ + j] = (s + bias[j]) * 0.125f;
}

// ---------------- sliding-window + global-key attention (tensor-core flash) -----
__global__ void __launch_bounds__(256) attn_kernel(
    const float* __restrict__ q, const float* __restrict__ k, const float* __restrict__ v,
    const int* __restrict__ mask, float* __restrict__ out) {
    const int c = blockIdx.x, hh = blockIdx.y, b = blockIdx.z;
    const int tid = threadIdx.x, lane = tid & 31, wid = tid >> 5;
    const int g = lane >> 2, t = lane & 3;
    const int wq = wid * 16;
    __shared__ float Ks[64 * 68];
    __shared__ float Vs[64 * 72];
    __shared__ float k0s[64], v0s[64];
    __shared__ int vld[64];

    const size_t hb = (size_t)b * S_ * D_ + hh * HD_;

    if (tid < 64) { k0s[tid] = k[hb + tid]; v0s[tid] = v[hb + tid]; }

    uint32_t Qf[8][4];
    {
        const float* qr0 = q + hb + (size_t)(c * W_ + wq + g) * D_;
        const float* qr1 = qr0 + 8 * D_;
#pragma unroll
        for (int kk = 0; kk < 8; kk++) {
            Qf[kk][0] = f2tf(qr0[kk * 8 + t]);
            Qf[kk][1] = f2tf(qr1[kk * 8 + t]);
            Qf[kk][2] = f2tf(qr0[kk * 8 + t + 4]);
            Qf[kk][3] = f2tf(qr1[kk * 8 + t + 4]);
        }
    }
    __syncthreads();

    float p0 = 0.f, p1 = 0.f;
#pragma unroll
    for (int kk = 0; kk < 8; kk++) {
        p0 += __uint_as_float(Qf[kk][0]) * k0s[kk*8 + t] + __uint_as_float(Qf[kk][2]) * k0s[kk*8 + t + 4];
        p1 += __uint_as_float(Qf[kk][1]) * k0s[kk*8 + t] + __uint_as_float(Qf[kk][3]) * k0s[kk*8 + t + 4];
    }
    p0 += __shfl_xor_sync(0xffffffffu, p0, 1); p0 += __shfl_xor_sync(0xffffffffu, p0, 2);
    p1 += __shfl_xor_sync(0xffffffffu, p1, 1); p1 += __shfl_xor_sync(0xffffffffu, p1, 2);

    const bool m0set = mask[(size_t)b * S_] != 0;
    float m0 = m0set ? p0 : -1e30f;
    float m1 = m0set ? p1 : -1e30f;
    float l0 = m0set ? 1.f : 0.f;
    float l1 = l0;
    float acc[8][4];
#pragma unroll
    for (int nt = 0; nt < 8; nt++) {
        float va = m0set ? v0s[nt*8 + 2*t]     : 0.f;
        float vb = m0set ? v0s[nt*8 + 2*t + 1] : 0.f;
        acc[nt][0] = va; acc[nt][1] = vb; acc[nt][2] = va; acc[nt][3] = vb;
    }

    const int base = c * W_ - W_;
    const int q0r = wq + g, q1r = q0r + 8;
    const uint32_t* Ku = (const uint32_t*)Ks;
    const uint32_t* Vu = (const uint32_t*)Vs;

    for (int tile = 0; tile < 6; tile++) {
        __syncthreads();
#pragma unroll
        for (int e = 0; e < 4; e++) {
            int id = tid + e * 256;
            int r = id >> 4, c4 = (id & 15) * 4;
            int p = base + tile * 64 + r;
            float4 kv = make_float4(0.f,0.f,0.f,0.f), vv = kv;
            if (p >= 0 && p < S_) {
                size_t off = hb + (size_t)p * D_ + c4;
                kv = *(const float4*)(k + off);
                vv = *(const float4*)(v + off);
            }
            uint32_t* kd = (uint32_t*)&Ks[r * 68 + c4];
            kd[0] = f2tf(kv.x); kd[1] = f2tf(kv.y); kd[2] = f2tf(kv.z); kd[3] = f2tf(kv.w);
            uint32_t* vd = (uint32_t*)&Vs[r * 72 + c4];
            vd[0] = f2tf(vv.x); vd[1] = f2tf(vv.y); vd[2] = f2tf(vv.z); vd[3] = f2tf(vv.w);
        }
        if (tid < 64) {
            int p = base + tile * 64 + tid;
            vld[tid] = (p >= 0 && p < S_) ? (mask[(size_t)b * S_ + p] != 0) : 0;
        }
        __syncthreads();

        float sc[8][4];
#pragma unroll
        for (int nt = 0; nt < 8; nt++) { sc[nt][0]=0.f; sc[nt][1]=0.f; sc[nt][2]=0.f; sc[nt][3]=0.f; }
#pragma unroll
        for (int kk = 0; kk < 8; kk++) {
#pragma unroll
            for (int nt = 0; nt < 8; nt++) {
                unsigned bf[2];
                bf[0] = Ku[(nt*8 + g) * 68 + kk*8 + t];
                bf[1] = Ku[(nt*8 + g) * 68 + kk*8 + t + 4];
                mma_tf32(sc[nt], Qf[kk], bf);
            }
        }

        float tm0 = -1e30f, tm1 = -1e30f;
#pragma unroll
        for (int nt = 0; nt < 8; nt++) {
            int j0 = tile*64 + nt*8 + 2*t, j1 = j0 + 1;
            bool ok00 = (j0 >= q0r) && (j0 <= q0r + 2*W_) && vld[nt*8 + 2*t];
            bool ok01 = (j1 >= q0r) && (j1 <= q0r + 2*W_) && vld[nt*8 + 2*t + 1];
            bool ok10 = (j0 >= q1r) && (j0 <= q1r + 2*W_) && vld[nt*8 + 2*t];
            bool ok11 = (j1 >= q1r) && (j1 <= q1r + 2*W_) && vld[nt*8 + 2*t + 1];
            sc[nt][0] = ok00 ? sc[nt][0] : -1e30f;
            sc[nt][1] = ok01 ? sc[nt][1] : -1e30f;
            sc[nt][2] = ok10 ? sc[nt][2] : -1e30f;
            sc[nt][3] = ok11 ? sc[nt][3] : -1e30f;
            tm0 = fmaxf(tm0, fmaxf(sc[nt][0], sc[nt][1]));
            tm1 = fmaxf(tm1, fmaxf(sc[nt][2], sc[nt][3]));
        }
        tm0 = fmaxf(tm0, __shfl_xor_sync(0xffffffffu, tm0, 1));
        tm0 = fmaxf(tm0, __shfl_xor_sync(0xffffffffu, tm0, 2));
        tm1 = fmaxf(tm1, __shfl_xor_sync(0xffffffffu, tm1, 1));
        tm1 = fmaxf(tm1, __shfl_xor_sync(0xffffffffu, tm1, 2));

        float nm0 = fmaxf(m0, tm0), nm1 = fmaxf(m1, tm1);
        float cr0 = __expf(m0 - nm0), cr1 = __expf(m1 - nm1);
        m0 = nm0; m1 = nm1; l0 *= cr0; l1 *= cr1;

        float ps0 = 0.f, ps1 = 0.f;
#pragma unroll
        for (int nt = 0; nt < 8; nt++) {
            sc[nt][0] = (sc[nt][0] > -1e29f) ? __expf(sc[nt][0] - m0) : 0.f;
            sc[nt][1] = (sc[nt][1] > -1e29f) ? __expf(sc[nt][1] - m0) : 0.f;
            sc[nt][2] = (sc[nt][2] > -1e29f) ? __expf(sc[nt][2] - m1) : 0.f;
            sc[nt][3] = (sc[nt][3] > -1e29f) ? __expf(sc[nt][3] - m1) : 0.f;
            ps0 += sc[nt][0] + sc[nt][1];
            ps1 += sc[nt][2] + sc[nt][3];
            acc[nt][0] *= cr0; acc[nt][1] *= cr0; acc[nt][2] *= cr1; acc[nt][3] *= cr1;
        }
        ps0 += __shfl_xor_sync(0xffffffffu, ps0, 1); ps0 += __shfl_xor_sync(0xffffffffu, ps0, 2);
        ps1 += __shfl_xor_sync(0xffffffffu, ps1, 1); ps1 += __shfl_xor_sync(0xffffffffu, ps1, 2);
        l0 += ps0; l1 += ps1;

        const int src0 = (lane & ~3) | (t >> 1);
        const int src1 = src0 + 2;
        const bool odd = t & 1;
#pragma unroll
        for (int kk = 0; kk < 8; kk++) {
            float x0 = __shfl_sync(0xffffffffu, sc[kk][0], src0);
            float x1 = __shfl_sync(0xffffffffu, sc[kk][1], src0);
            float x2 = __shfl_sync(0xffffffffu, sc[kk][2], src0);
            float x3 = __shfl_sync(0xffffffffu, sc[kk][3], src0);
            float y0 = __shfl_sync(0xffffffffu, sc[kk][0], src1);
            float y1 = __shfl_sync(0xffffffffu, sc[kk][1], src1);
            float y2 = __shfl_sync(0xffffffffu, sc[kk][2], src1);
            float y3 = __shfl_sync(0xffffffffu, sc[kk][3], src1);
            unsigned af[4];
            af[0] = f2tf(odd ? x1 : x0);
            af[1] = f2tf(odd ? x3 : x2);
            af[2] = f2tf(odd ? y1 : y0);
            af[3] = f2tf(odd ? y3 : y2);
#pragma unroll
            for (int nt = 0; nt < 8; nt++) {
                unsigned bf[2];
                bf[0] = Vu[(kk*8 + t) * 72 + nt*8 + g];
                bf[1] = Vu[(kk*8 + t + 4) * 72 + nt*8 + g];
                mma_tf32(acc[nt], af, bf);
            }
        }
    }

    float inv0 = 1.f / l0, inv1 = 1.f / l1;
    float* or0 = out + hb + (size_t)(c * W_ + wq + g) * D_;
    float* or1 = or0 + 8 * D_;
#pragma unroll
    for (int nt = 0; nt < 8; nt++) {
        *(float2*)(or0 + nt*8 + 2*t) = make_float2(acc[nt][0] * inv0, acc[nt][1] * inv0);
        *(float2*)(or1 + nt*8 + 2*t) = make_float2(acc[nt][2] * inv1, acc[nt][3] * inv1);
    }
}

// ---------------- global-token attention -> overwrite out row 0 (1024 thr) ------
__global__ void __launch_bounds__(1024) gattn_kernel(
    const float* __restrict__ qg, const float* __restrict__ kg,
    const float* __restrict__ vg, const int* __restrict__ mask,
    float* __restrict__ out) {
    const int hh = blockIdx.x, b = blockIdx.y;
    const int tid = threadIdx.x;
    const int lane = tid & 31, wrp = tid >> 5;
    __shared__ float sc[S_];
    __shared__ float qs[HD_];
    __shared__ float r1[32];
    __shared__ float stat[2];
    __shared__ float accb[16][HD_];
    if (tid < HD_) qs[tid] = qg[b * D_ + hh * HD_ + tid];
    __syncthreads();
    float lmax = -3.4e38f;
    for (int s = tid; s < S_; s += 1024) {
        const float4* kr = (const float4*)(kg + ((size_t)b * S_ + s) * D_ + hh * HD_);
        float dot = 0.f;
#pragma unroll
        for (int i = 0; i < 16; i++) {
            float4 k4 = kr[i];
            dot = fmaf(qs[i*4], k4.x, dot);   dot = fmaf(qs[i*4+1], k4.y, dot);
            dot = fmaf(qs[i*4+2], k4.z, dot); dot = fmaf(qs[i*4+3], k4.w, dot);
        }
        if (mask[(size_t)b * S_ + s] == 0) dot = -1e9f;
        sc[s] = dot;
        lmax = fmaxf(lmax, dot);
    }
#pragma unroll
    for (int o = 16; o > 0; o >>= 1) lmax = fmaxf(lmax, __shfl_down_sync(0xffffffffu, lmax, o));
    if (lane == 0) r1[wrp] = lmax;
    __syncthreads();
    if (wrp == 0) {
        float m2 = r1[lane];
#pragma unroll
        for (int o = 16; o > 0; o >>= 1) m2 = fmaxf(m2, __shfl_down_sync(0xffffffffu, m2, o));
        if (lane == 0) stat[0] = m2;
    }
    __syncthreads();
    float gmax = stat[0];
    float lsum = 0.f;
    for (int s = tid; s < S_; s += 1024) {
        float e = __expf(sc[s] - gmax);
        sc[s] = e;
        lsum += e;
    }
#pragma unroll
    for (int o = 16; o > 0; o >>= 1) lsum += __shfl_down_sync(0xffffffffu, lsum, o);
    if (lane == 0) r1[wrp] = lsum;
    __syncthreads();
    if (wrp == 0) {
        float s2 = r1[lane];
#pragma unroll
        for (int o = 16; o > 0; o >>= 1) s2 += __shfl_down_sync(0xffffffffu, s2, o);
        if (lane == 0) stat[1] = s2;
    }
    __syncthreads();
    float inv = 1.f / stat[1];
    int d = tid & 63, part = tid >> 6;          // 16 partitions x 64 dims
    float a = 0.f;
    for (int s = part; s < S_; s += 16)
        a = fmaf(sc[s], vg[((size_t)b * S_ + s) * D_ + hh * HD_ + d], a);
    accb[part][d] = a;
    __syncthreads();
    if (tid < HD_) {
        float r = 0.f;
#pragma unroll
        for (int p = 0; p < 16; p++) r += accb[p][tid];
        out[(size_t)b * S_ * D_ + hh * HD_ + tid] = r * inv;
    }
}

// ---------------- classifier head ----------------
__global__ void cls_kernel(const float* __restrict__ h, const float* __restrict__ Wcls,
                           const float* __restrict__ bcls, const int* __restrict__ mask,
                           float* __restrict__ out) {
    int w = threadIdx.x >> 5, lane = threadIdx.x & 31;
    int b = w & 1, j = w >> 1;
    float s = 0.f;
    for (int kk = lane; kk < D_; kk += 32)
        s = fmaf(h[(size_t)b * S_ * D_ + kk], Wcls[kk * 3 + j], s);
#pragma unroll
    for (int o = 16; o > 0; o >>= 1) s += __shfl_down_sync(0xffffffffu, s, o);
    if (lane == 0) out[j * 2 + b] = 1.f / (1.f + expf(-(s + bcls[j])));
    if (threadIdx.x < 2) out[6 + threadIdx.x] = (float)mask[(size_t)threadIdx.x * S_];
}

// ---------------- launch ----------------
extern "C" void kernel_launch(void* const* d_in, const int* in_sizes, int n_in,
                              void* d_out, int out_size) {
    const int*   src  = (const int*)d_in[0];
    const int*   mask = (const int*)d_in[1];
    const float* etok = (const float*)d_in[3];
    const float* epos = (const float*)d_in[4];
    const float* elns = (const float*)d_in[5];
    const float* elnb = (const float*)d_in[6];
    const float* Wq   = (const float*)d_in[7];   const float* bq_p  = (const float*)d_in[8];
    const float* Wk   = (const float*)d_in[9];   const float* bk_p  = (const float*)d_in[10];
    const float* Wv   = (const float*)d_in[11];  const float* bv_p  = (const float*)d_in[12];
    const float* Wo   = (const float*)d_in[13];  const float* bo_p  = (const float*)d_in[14];
    const float* Wqg  = (const float*)d_in[15];  const float* bqg_p = (const float*)d_in[16];
    const float* Wkg  = (const float*)d_in[17];  const float* bkg_p = (const float*)d_in[18];
    const float* Wvg  = (const float*)d_in[19];  const float* bvg_p = (const float*)d_in[20];
    const float* ln1s = (const float*)d_in[21];  const float* ln1b  = (const float*)d_in[22];
    const float* W1   = (const float*)d_in[23];  const float* b1_p  = (const float*)d_in[24];
    const float* W2   = (const float*)d_in[25];  const float* b2_p  = (const float*)d_in[26];
    const float* ln2s = (const float*)d_in[27];  const float* ln2b  = (const float*)d_in[28];
    const float* Wcls = (const float*)d_in[29];  const float* bcls  = (const float*)d_in[30];
    float* out = (float*)d_out;

    float *ph, *pq, *pk, *pv, *pkg, *pvg, *pa, *pt, *pf, *pqg;
    cudaGetSymbolAddress((void**)&ph,  g_h);
    cudaGetSymbolAddress((void**)&pq,  g_q);
    cudaGetSymbolAddress((void**)&pk,  g_k);
    cudaGetSymbolAddress((void**)&pv,  g_v);
    cudaGetSymbolAddress((void**)&pkg, g_kg);
    cudaGetSymbolAddress((void**)&pvg, g_vg);
    cudaGetSymbolAddress((void**)&pa,  g_a);
    cudaGetSymbolAddress((void**)&pt,  g_t);
    cudaGetSymbolAddress((void**)&pf,  g_ff);
    cudaGetSymbolAddress((void**)&pqg, g_qg);

    const int M = B_ * S_;   // 4096

    embed_ln_kernel<<<M, 256>>>(src, etok, epos, elns, elnb, ph);

    for (int l = 0; l < L_; l++) {
        size_t wo  = (size_t)l * D_ * D_;
        size_t bof = (size_t)l * D_;

        ProjParams pp;
        pp.W[0] = Wq  + wo; pp.b[0] = bq_p  + bof; pp.o[0] = pq;  pp.alpha[0] = 0.125f;
        pp.W[1] = Wk  + wo; pp.b[1] = bk_p  + bof; pp.o[1] = pk;  pp.alpha[1] = 1.f;
        pp.W[2] = Wv  + wo; pp.b[2] = bv_p  + bof; pp.o[2] = pv;  pp.alpha[2] = 1.f;
        pp.W[3] = Wkg + wo; pp.b[3] = bkg_p + bof; pp.o[3] = pkg; pp.alpha[3] = 1.f;
        pp.W[4] = Wvg + wo; pp.b[4] = bvg_p + bof; pp.o[4] = pvg; pp.alpha[4] = 1.f;
        proj_gemm_kernel<<<dim3(D_ / 128, M / 128, 5), 128>>>(ph, pp, M, D_, D_);

        qg_kernel<<<dim3(B_, 3), 256>>>(ph, Wqg + wo, bqg_p + bof, pqg);
        attn_kernel<<<dim3(NC_, H_, B_), 256>>>(pq, pk, pv, mask, pa);
        gattn_kernel<<<dim3(H_, B_), 1024>>>(pqg, pkg, pvg, mask, pa);

        tgemm_kernel<0><<<dim3(D_ / 128, M / 128), 128>>>(pa, Wo + wo, bo_p + bof, pt, M, D_, D_, 1.f);
        add_ln_kernel<<<M, 256>>>(ph, pt, ln1s + bof, ln1b + bof);
        tgemm_kernel<1><<<dim3(FF_ / 128, M / 128), 128>>>(ph, W1 + (size_t)l * D_ * FF_,
                                                           b1_p + (size_t)l * FF_, pf, M, FF_, D_, 1.f);
        tgemm_kernel<0><<<dim3(D_ / 128, M / 128), 128>>>(pf, W2 + (size_t)l * FF_ * D_,
                                                          b2_p + bof, pt, M, D_, FF_, 1.f);
        add_ln_kernel<<<M, 256>>>(ph, pt, ln2s + bof, ln2b + bof);
    }

    cls_kernel<<<1, 192>>>(ph, Wcls, bcls, mask, out);
}

// round 12
// speedup vs baseline: 1.7155x; 1.0177x over previous
#include <cuda_runtime.h>
#include <math.h>
#include <stdint.h>

#define B_  2
#define S_  2048
#define D_  768
#define H_  12
#define HD_ 64
#define L_  4
#define FF_ 3072
#define NC_ 16
#define W_  128

// ---------------- scratch (static device arrays; no allocation) ----------------
__device__ float g_h [B_*S_*D_];
__device__ float g_q [B_*S_*D_];
__device__ float g_k [B_*S_*D_];
__device__ float g_v [B_*S_*D_];
__device__ float g_kg[B_*S_*D_];
__device__ float g_vg[B_*S_*D_];
__device__ float g_a [B_*S_*D_];
__device__ float g_t [B_*S_*D_];
__device__ float g_ff[B_*S_*FF_];
__device__ float g_qg[B_*D_];

// ---------------- helpers ----------------
__device__ __forceinline__ uint32_t smem_u32(const void* p) {
    return (uint32_t)__cvta_generic_to_shared(p);
}
__device__ __forceinline__ void cp16(uint32_t dst, const void* src) {
    asm volatile("cp.async.cg.shared.global [%0], [%1], 16;" :: "r"(dst), "l"(src));
}
__device__ __forceinline__ void cp_commit() { asm volatile("cp.async.commit_group;"); }
template <int N> __device__ __forceinline__ void cp_wait() {
    asm volatile("cp.async.wait_group %0;" :: "n"(N));
}
__device__ __forceinline__ uint32_t f2tf(float x) {
    uint32_t r;
    asm("cvt.rna.tf32.f32 %0, %1;" : "=r"(r) : "f"(x));
    return r;
}
__device__ __forceinline__ void ldsm4(uint32_t addr, unsigned* r) {
    asm volatile("ldmatrix.sync.aligned.m8n8.x4.shared.b16 {%0,%1,%2,%3}, [%4];"
        : "=r"(r[0]), "=r"(r[1]), "=r"(r[2]), "=r"(r[3]) : "r"(addr));
}

__device__ __forceinline__ void mma_tf32(float* c, const unsigned* a, const unsigned* b) {
    asm volatile(
        "mma.sync.aligned.m16n8k8.row.col.f32.tf32.tf32.f32 "
        "{%0,%1,%2,%3}, {%4,%5,%6,%7}, {%8,%9}, {%0,%1,%2,%3};"
        : "+f"(c[0]), "+f"(c[1]), "+f"(c[2]), "+f"(c[3])
        : "r"(a[0]), "r"(a[1]), "r"(a[2]), "r"(a[3]), "r"(b[0]), "r"(b[1]));
}

__device__ __forceinline__ void block_reduce2(float a, float b, float* out2) {
    __shared__ float r1[8], r2[8];
    int lane = threadIdx.x & 31, wid = threadIdx.x >> 5;
#pragma unroll
    for (int o = 16; o > 0; o >>= 1) {
        a += __shfl_down_sync(0xffffffffu, a, o);
        b += __shfl_down_sync(0xffffffffu, b, o);
    }
    if (lane == 0) { r1[wid] = a; r2[wid] = b; }
    __syncthreads();
    if (wid == 0) {
        int nw = blockDim.x >> 5;
        a = (lane < nw) ? r1[lane] : 0.f;
        b = (lane < nw) ? r2[lane] : 0.f;
#pragma unroll
        for (int o = 4; o > 0; o >>= 1) {
            a += __shfl_down_sync(0xffffffffu, a, o);
            b += __shfl_down_sync(0xffffffffu, b, o);
        }
        if (lane == 0) { out2[0] = a; out2[1] = b; }
    }
    __syncthreads();
}

// ---------------- tf32 GEMM: BK=32, 3-stage cp.async ---------------------------
// C = act((A@B + bias) * alpha); A: MxK rm, B: KxN rm. M%128==N%128==K%32==0.
// Block 128x128x32, 128 thr, 4 warps 2x2 (warp tile 64x64).
// A stage: 128 rows x 32 words (128B rows), chunk swizzle c^(row&7) -> conflict-
// free cp.async stores AND ldmatrix reads. B stage: 32 rows x 136 words.
// Dynamic smem: 3*(16KB + 17KB) = 99KB; 2 blocks/SM = 198KB <= 228KB.
#define GEMM_ASTG (128 * 32)
#define GEMM_BSTG (32 * 136)
#define GEMM_SMEM (3 * (GEMM_ASTG + GEMM_BSTG) * 4)

template <int ACT>
__device__ __forceinline__ void gemm_core(
    const float* __restrict__ A, const float* __restrict__ Bm,
    const float* __restrict__ bias, float* __restrict__ C,
    int M, int N, int K, float alpha) {
    extern __shared__ uint32_t dyn[];
    uint32_t* As = dyn;
    uint32_t* Bs = dyn + 3 * GEMM_ASTG;

    const int tid = threadIdx.x, lane = tid & 31, wid = tid >> 5;
    const int wm = (wid >> 1) * 64, wn = (wid & 1) * 64;
    const int g = lane >> 2, t = lane & 3;
    const int bm = blockIdx.y * 128, bn = blockIdx.x * 128;

    // cp.async bases (8 slots each derived by constant offsets)
    const float* aP = A + (size_t)(bm + (tid >> 3)) * K + (tid & 7) * 4;
    const float* bP = Bm + (size_t)(tid >> 5) * N + bn + (tid & 31) * 4;
    const uint32_t aD0 = smem_u32(As) + ((tid >> 3) << 7)
                       + ((((tid & 7) ^ ((tid >> 3) & 7))) << 4);
    const uint32_t bD0 = smem_u32(Bs) + (((tid >> 5) * 136 + (tid & 31) * 4) << 2);

    // ldmatrix A lane address
    const int lm = lane >> 3, lr = lane & 7;
    const uint32_t aLd = smem_u32(As) + ((wm + (lm & 1) * 8 + lr) << 7);
    const int csel = lm >> 1;

    float acc[4][8][4];
#pragma unroll
    for (int i = 0; i < 4; i++)
#pragma unroll
        for (int j = 0; j < 8; j++)
#pragma unroll
            for (int r = 0; r < 4; r++) acc[i][j][r] = 0.f;

    const int nk = K >> 5;

    auto issue = [&](int kt) {
        const int s = kt % 3;
        const int k0 = kt << 5;
        const float* ap = aP + k0;
        const float* bp = bP + (size_t)k0 * N;
        const uint32_t ad = aD0 + s * (GEMM_ASTG * 4);
        const uint32_t bd = bD0 + s * (GEMM_BSTG * 4);
#pragma unroll
        for (int i = 0; i < 8; i++) {
            cp16(ad + i * 2048, ap + (size_t)(i * 16) * K);
            cp16(bd + i * 2176, bp + (size_t)(i * 4) * N);
        }
        cp_commit();
    };

    issue(0);
    if (nk > 1) issue(1);

    for (int kt = 0; kt < nk; kt++) {
        if (kt + 1 == nk) cp_wait<0>(); else cp_wait<1>();
        __syncthreads();
        if (kt + 2 < nk) issue(kt + 2);

        const uint32_t sa = aLd + (kt % 3) * (GEMM_ASTG * 4);
        const uint32_t* sB = &Bs[(kt % 3) * GEMM_BSTG];
#pragma unroll
        for (int ks = 0; ks < 4; ks++) {
            const int kb = ks * 8;
            const uint32_t aoff = (uint32_t)((((2 * ks + csel) ^ lr) & 7) << 4);
            unsigned af[4][4], bf[8][2];
#pragma unroll
            for (int mt = 0; mt < 4; mt++)
                ldsm4(sa + mt * 2048 + aoff, af[mt]);   // 16 rows * 128B = 2048
#pragma unroll
            for (int nt = 0; nt < 8; nt++) {
                int cc = wn + nt * 8 + g;
                bf[nt][0] = sB[(kb + t) * 136 + cc];
                bf[nt][1] = sB[(kb + t + 4) * 136 + cc];
            }
#pragma unroll
            for (int mt = 0; mt < 4; mt++)
#pragma unroll
                for (int nt = 0; nt < 8; nt++)
                    mma_tf32(acc[mt][nt], af[mt], bf[nt]);
        }
        __syncthreads();
    }

    // epilogue
#pragma unroll
    for (int mt = 0; mt < 4; mt++) {
#pragma unroll
        for (int nt = 0; nt < 8; nt++) {
            int r0 = bm + wm + mt * 16 + g;
            int c0 = bn + wn + nt * 8 + t * 2;
            float b0 = bias[c0], b1 = bias[c0 + 1];
            float v[4];
            v[0] = (acc[mt][nt][0] + b0) * alpha;
            v[1] = (acc[mt][nt][1] + b1) * alpha;
            v[2] = (acc[mt][nt][2] + b0) * alpha;
            v[3] = (acc[mt][nt][3] + b1) * alpha;
            if (ACT == 1) {
#pragma unroll
                for (int i = 0; i < 4; i++)
                    v[i] = 0.5f * v[i] * (1.f + erff(v[i] * 0.7071067811865476f));
            }
            *(float2*)(C + (size_t)r0 * N + c0)       = make_float2(v[0], v[1]);
            *(float2*)(C + (size_t)(r0 + 8) * N + c0) = make_float2(v[2], v[3]);
        }
    }
}

template <int ACT>
__global__ void __launch_bounds__(128, 2) tgemm_kernel(
    const float* __restrict__ A, const float* __restrict__ Bm,
    const float* __restrict__ bias, float* __restrict__ C,
    int M, int N, int K, float alpha) {
    gemm_core<ACT>(A, Bm, bias, C, M, N, K, alpha);
}

struct ProjParams {
    const float* W[5];
    const float* b[5];
    float*       o[5];
    float        alpha[5];
};

__global__ void __launch_bounds__(128, 2) proj_gemm_kernel(
    const float* __restrict__ A, ProjParams p, int M, int N, int K) {
    int z = blockIdx.z;
    gemm_core<0>(A, p.W[z], p.b[z], p.o[z], M, N, K, p.alpha[z]);
}

// ---------------- embedding + LN ----------------
__global__ void embed_ln_kernel(const int* __restrict__ src,
                                const float* __restrict__ etok,
                                const float* __restrict__ epos,
                                const float* __restrict__ gs,
                                const float* __restrict__ gb,
                                float* __restrict__ h) {
    int tok = blockIdx.x;
    int s   = tok & (S_ - 1);
    int tid = threadIdx.x;
    __shared__ float stat[2];
    size_t row = (size_t)src[tok] * D_;
    float vals[3]; float sum = 0.f, sq = 0.f;
#pragma unroll
    for (int i = 0; i < 3; i++) {
        int d = tid + i * 256;
        float v = etok[row + d] + epos[(size_t)s * D_ + d];
        vals[i] = v; sum += v; sq += v * v;
    }
    block_reduce2(sum, sq, stat);
    float mean = stat[0] * (1.f / D_);
    float var  = stat[1] * (1.f / D_) - mean * mean;
    float inv  = 1.f / sqrtf(var + 1e-5f);
#pragma unroll
    for (int i = 0; i < 3; i++) {
        int d = tid + i * 256;
        h[(size_t)tok * D_ + d] = (vals[i] - mean) * inv * gs[d] + gb[d];
    }
}

// ---------------- residual add + LN (in place on h) ----------------
__global__ void add_ln_kernel(float* __restrict__ h, const float* __restrict__ x,
                              const float* __restrict__ sc, const float* __restrict__ bi) {
    int tok = blockIdx.x;
    int tid = threadIdx.x;
    __shared__ float stat[2];
    float* hp = h + (size_t)tok * D_;
    const float* xp = x + (size_t)tok * D_;
    float vals[3]; float sum = 0.f, sq = 0.f;
#pragma unroll
    for (int i = 0; i < 3; i++) {
        int d = tid + i * 256;
        float v = hp[d] + xp[d];
        vals[i] = v; sum += v; sq += v * v;
    }
    block_reduce2(sum, sq, stat);
    float mean = stat[0] * (1.f / D_);
    float var  = stat[1] * (1.f / D_) - mean * mean;
    float inv  = 1.f / sqrtf(var + 1e-5f);
#pragma unroll
    for (int i = 0; i < 3; i++) {
        int d = tid + i * 256;
        hp[d] = (vals[i] - mean) * inv * sc[d] + bi[d];
    }
}

// ---------------- qg = (h[:,0,:] @ Wqg + bqg) / 8 ----------------
__global__ void qg_kernel(const float* __restrict__ h, const float* __restrict__ Wm,
                          const float* __restrict__ bias, float* __restrict__ qg) {
    int b = blockIdx.x;
    int j = blockIdx.y * 256 + threadIdx.x;
    __shared__ float hs[D_];
    for (int i = threadIdx.x; i < D_; i += 256) hs[i] = h[(size_t)b * S_ * D_ + i];
    __syncthreads();
    float s = 0.f;
    for (int kk = 0; kk < D_; kk++) s = fmaf(hs[kk], Wm[(size_t)kk * D_ + j], s);
    qg[b * D_ + j] = (s + bias[j]) * 0.125f;
}

// ---------------- sliding-window + global-key attention (tensor-core flash) -----
__global__ void __launch_bounds__(256) attn_kernel(
    const float* __restrict__ q, const float* __restrict__ k, const float* __restrict__ v,
    const int* __restrict__ mask, float* __restrict__ out) {
    const int c = blockIdx.x, hh = blockIdx.y, b = blockIdx.z;
    const int tid = threadIdx.x, lane = tid & 31, wid = tid >> 5;
    const int g = lane >> 2, t = lane & 3;
    const int wq = wid * 16;
    __shared__ float Ks[64 * 68];
    __shared__ float Vs[64 * 72];
    __shared__ float k0s[64], v0s[64];
    __shared__ int vld[64];

    const size_t hb = (size_t)b * S_ * D_ + hh * HD_;

    if (tid < 64) { k0s[tid] = k[hb + tid]; v0s[tid] = v[hb + tid]; }

    uint32_t Qf[8][4];
    {
        const float* qr0 = q + hb + (size_t)(c * W_ + wq + g) * D_;
        const float* qr1 = qr0 + 8 * D_;
#pragma unroll
        for (int kk = 0; kk < 8; kk++) {
            Qf[kk][0] = f2tf(qr0[kk * 8 + t]);
            Qf[kk][1] = f2tf(qr1[kk * 8 + t]);
            Qf[kk][2] = f2tf(qr0[kk * 8 + t + 4]);
            Qf[kk][3] = f2tf(qr1[kk * 8 + t + 4]);
        }
    }
    __syncthreads();

    float p0 = 0.f, p1 = 0.f;
#pragma unroll
    for (int kk = 0; kk < 8; kk++) {
        p0 += __uint_as_float(Qf[kk][0]) * k0s[kk*8 + t] + __uint_as_float(Qf[kk][2]) * k0s[kk*8 + t + 4];
        p1 += __uint_as_float(Qf[kk][1]) * k0s[kk*8 + t] + __uint_as_float(Qf[kk][3]) * k0s[kk*8 + t + 4];
    }
    p0 += __shfl_xor_sync(0xffffffffu, p0, 1); p0 += __shfl_xor_sync(0xffffffffu, p0, 2);
    p1 += __shfl_xor_sync(0xffffffffu, p1, 1); p1 += __shfl_xor_sync(0xffffffffu, p1, 2);

    const bool m0set = mask[(size_t)b * S_] != 0;
    float m0 = m0set ? p0 : -1e30f;
    float m1 = m0set ? p1 : -1e30f;
    float l0 = m0set ? 1.f : 0.f;
    float l1 = l0;
    float acc[8][4];
#pragma unroll
    for (int nt = 0; nt < 8; nt++) {
        float va = m0set ? v0s[nt*8 + 2*t]     : 0.f;
        float vb = m0set ? v0s[nt*8 + 2*t + 1] : 0.f;
        acc[nt][0] = va; acc[nt][1] = vb; acc[nt][2] = va; acc[nt][3] = vb;
    }

    const int base = c * W_ - W_;
    const int q0r = wq + g, q1r = q0r + 8;
    const uint32_t* Ku = (const uint32_t*)Ks;
    const uint32_t* Vu = (const uint32_t*)Vs;

    for (int tile = 0; tile < 6; tile++) {
        __syncthreads();
#pragma unroll
        for (int e = 0; e < 4; e++) {
            int id = tid + e * 256;
            int r = id >> 4, c4 = (id & 15) * 4;
            int p = base + tile * 64 + r;
            float4 kv = make_float4(0.f,0.f,0.f,0.f), vv = kv;
            if (p >= 0 && p < S_) {
                size_t off = hb + (size_t)p * D_ + c4;
                kv = *(const float4*)(k + off);
                vv = *(const float4*)(v + off);
            }
            uint32_t* kd = (uint32_t*)&Ks[r * 68 + c4];
            kd[0] = f2tf(kv.x); kd[1] = f2tf(kv.y); kd[2] = f2tf(kv.z); kd[3] = f2tf(kv.w);
            uint32_t* vd = (uint32_t*)&Vs[r * 72 + c4];
            vd[0] = f2tf(vv.x); vd[1] = f2tf(vv.y); vd[2] = f2tf(vv.z); vd[3] = f2tf(vv.w);
        }
        if (tid < 64) {
            int p = base + tile * 64 + tid;
            vld[tid] = (p >= 0 && p < S_) ? (mask[(size_t)b * S_ + p] != 0) : 0;
        }
        __syncthreads();

        float sc[8][4];
#pragma unroll
        for (int nt = 0; nt < 8; nt++) { sc[nt][0]=0.f; sc[nt][1]=0.f; sc[nt][2]=0.f; sc[nt][3]=0.f; }
#pragma unroll
        for (int kk = 0; kk < 8; kk++) {
#pragma unroll
            for (int nt = 0; nt < 8; nt++) {
                unsigned bf[2];
                bf[0] = Ku[(nt*8 + g) * 68 + kk*8 + t];
                bf[1] = Ku[(nt*8 + g) * 68 + kk*8 + t + 4];
                mma_tf32(sc[nt], Qf[kk], bf);
            }
        }

        float tm0 = -1e30f, tm1 = -1e30f;
#pragma unroll
        for (int nt = 0; nt < 8; nt++) {
            int j0 = tile*64 + nt*8 + 2*t, j1 = j0 + 1;
            bool ok00 = (j0 >= q0r) && (j0 <= q0r + 2*W_) && vld[nt*8 + 2*t];
            bool ok01 = (j1 >= q0r) && (j1 <= q0r + 2*W_) && vld[nt*8 + 2*t + 1];
            bool ok10 = (j0 >= q1r) && (j0 <= q1r + 2*W_) && vld[nt*8 + 2*t];
            bool ok11 = (j1 >= q1r) && (j1 <= q1r + 2*W_) && vld[nt*8 + 2*t + 1];
            sc[nt][0] = ok00 ? sc[nt][0] : -1e30f;
            sc[nt][1] = ok01 ? sc[nt][1] : -1e30f;
            sc[nt][2] = ok10 ? sc[nt][2] : -1e30f;
            sc[nt][3] = ok11 ? sc[nt][3] : -1e30f;
            tm0 = fmaxf(tm0, fmaxf(sc[nt][0], sc[nt][1]));
            tm1 = fmaxf(tm1, fmaxf(sc[nt][2], sc[nt][3]));
        }
        tm0 = fmaxf(tm0, __shfl_xor_sync(0xffffffffu, tm0, 1));
        tm0 = fmaxf(tm0, __shfl_xor_sync(0xffffffffu, tm0, 2));
        tm1 = fmaxf(tm1, __shfl_xor_sync(0xffffffffu, tm1, 1));
        tm1 = fmaxf(tm1, __shfl_xor_sync(0xffffffffu, tm1, 2));

        float nm0 = fmaxf(m0, tm0), nm1 = fmaxf(m1, tm1);
        float cr0 = __expf(m0 - nm0), cr1 = __expf(m1 - nm1);
        m0 = nm0; m1 = nm1; l0 *= cr0; l1 *= cr1;

        float ps0 = 0.f, ps1 = 0.f;
#pragma unroll
        for (int nt = 0; nt < 8; nt++) {
            sc[nt][0] = (sc[nt][0] > -1e29f) ? __expf(sc[nt][0] - m0) : 0.f;
            sc[nt][1] = (sc[nt][1] > -1e29f) ? __expf(sc[nt][1] - m0) : 0.f;
            sc[nt][2] = (sc[nt][2] > -1e29f) ? __expf(sc[nt][2] - m1) : 0.f;
            sc[nt][3] = (sc[nt][3] > -1e29f) ? __expf(sc[nt][3] - m1) : 0.f;
            ps0 += sc[nt][0] + sc[nt][1];
            ps1 += sc[nt][2] + sc[nt][3];
            acc[nt][0] *= cr0; acc[nt][1] *= cr0; acc[nt][2] *= cr1; acc[nt][3] *= cr1;
        }
        ps0 += __shfl_xor_sync(0xffffffffu, ps0, 1); ps0 += __shfl_xor_sync(0xffffffffu, ps0, 2);
        ps1 += __shfl_xor_sync(0xffffffffu, ps1, 1); ps1 += __shfl_xor_sync(0xffffffffu, ps1, 2);
        l0 += ps0; l1 += ps1;

        const int src0 = (lane & ~3) | (t >> 1);
        const int src1 = src0 + 2;
        const bool odd = t & 1;
#pragma unroll
        for (int kk = 0; kk < 8; kk++) {
            float x0 = __shfl_sync(0xffffffffu, sc[kk][0], src0);
            float x1 = __shfl_sync(0xffffffffu, sc[kk][1], src0);
            float x2 = __shfl_sync(0xffffffffu, sc[kk][2], src0);
            float x3 = __shfl_sync(0xffffffffu, sc[kk][3], src0);
            float y0 = __shfl_sync(0xffffffffu, sc[kk][0], src1);
            float y1 = __shfl_sync(0xffffffffu, sc[kk][1], src1);
            float y2 = __shfl_sync(0xffffffffu, sc[kk][2], src1);
            float y3 = __shfl_sync(0xffffffffu, sc[kk][3], src1);
            unsigned af[4];
            af[0] = f2tf(odd ? x1 : x0);
            af[1] = f2tf(odd ? x3 : x2);
            af[2] = f2tf(odd ? y1 : y0);
            af[3] = f2tf(odd ? y3 : y2);
#pragma unroll
            for (int nt = 0; nt < 8; nt++) {
                unsigned bf[2];
                bf[0] = Vu[(kk*8 + t) * 72 + nt*8 + g];
                bf[1] = Vu[(kk*8 + t + 4) * 72 + nt*8 + g];
                mma_tf32(acc[nt], af, bf);
            }
        }
    }

    float inv0 = 1.f / l0, inv1 = 1.f / l1;
    float* or0 = out + hb + (size_t)(c * W_ + wq + g) * D_;
    float* or1 = or0 + 8 * D_;
#pragma unroll
    for (int nt = 0; nt < 8; nt++) {
        *(float2*)(or0 + nt*8 + 2*t) = make_float2(acc[nt][0] * inv0, acc[nt][1] * inv0);
        *(float2*)(or1 + nt*8 + 2*t) = make_float2(acc[nt][2] * inv1, acc[nt][3] * inv1);
    }
}

// ---------------- global-token attention -> overwrite out row 0 (1024 thr) ------
__global__ void __launch_bounds__(1024) gattn_kernel(
    const float* __restrict__ qg, const float* __restrict__ kg,
    const float* __restrict__ vg, const int* __restrict__ mask,
    float* __restrict__ out) {
    const int hh = blockIdx.x, b = blockIdx.y;
    const int tid = threadIdx.x;
    const int lane = tid & 31, wrp = tid >> 5;
    __shared__ float sc[S_];
    __shared__ float qs[HD_];
    __shared__ float r1[32];
    __shared__ float stat[2];
    __shared__ float accb[16][HD_];
    if (tid < HD_) qs[tid] = qg[b * D_ + hh * HD_ + tid];
    __syncthreads();
    float lmax = -3.4e38f;
    for (int s = tid; s < S_; s += 1024) {
        const float4* kr = (const float4*)(kg + ((size_t)b * S_ + s) * D_ + hh * HD_);
        float dot = 0.f;
#pragma unroll
        for (int i = 0; i < 16; i++) {
            float4 k4 = kr[i];
            dot = fmaf(qs[i*4], k4.x, dot);   dot = fmaf(qs[i*4+1], k4.y, dot);
            dot = fmaf(qs[i*4+2], k4.z, dot); dot = fmaf(qs[i*4+3], k4.w, dot);
        }
        if (mask[(size_t)b * S_ + s] == 0) dot = -1e9f;
        sc[s] = dot;
        lmax = fmaxf(lmax, dot);
    }
#pragma unroll
    for (int o = 16; o > 0; o >>= 1) lmax = fmaxf(lmax, __shfl_down_sync(0xffffffffu, lmax, o));
    if (lane == 0) r1[wrp] = lmax;
    __syncthreads();
    if (wrp == 0) {
        float m2 = r1[lane];
#pragma unroll
        for (int o = 16; o > 0; o >>= 1) m2 = fmaxf(m2, __shfl_down_sync(0xffffffffu, m2, o));
        if (lane == 0) stat[0] = m2;
    }
    __syncthreads();
    float gmax = stat[0];
    float lsum = 0.f;
    for (int s = tid; s < S_; s += 1024) {
        float e = __expf(sc[s] - gmax);
        sc[s] = e;
        lsum += e;
    }
#pragma unroll
    for (int o = 16; o > 0; o >>= 1) lsum += __shfl_down_sync(0xffffffffu, lsum, o);
    if (lane == 0) r1[wrp] = lsum;
    __syncthreads();
    if (wrp == 0) {
        float s2 = r1[lane];
#pragma unroll
        for (int o = 16; o > 0; o >>= 1) s2 += __shfl_down_sync(0xffffffffu, s2, o);
        if (lane == 0) stat[1] = s2;
    }
    __syncthreads();
    float inv = 1.f / stat[1];
    int d = tid & 63, part = tid >> 6;
    float a = 0.f;
    for (int s = part; s < S_; s += 16)
        a = fmaf(sc[s], vg[((size_t)b * S_ + s) * D_ + hh * HD_ + d], a);
    accb[part][d] = a;
    __syncthreads();
    if (tid < HD_) {
        float r = 0.f;
#pragma unroll
        for (int p = 0; p < 16; p++) r += accb[p][tid];
        out[(size_t)b * S_ * D_ + hh * HD_ + tid] = r * inv;
    }
}

// ---------------- classifier head ----------------
__global__ void cls_kernel(const float* __restrict__ h, const float* __restrict__ Wcls,
                           const float* __restrict__ bcls, const int* __restrict__ mask,
                           float* __restrict__ out) {
    int w = threadIdx.x >> 5, lane = threadIdx.x & 31;
    int b = w & 1, j = w >> 1;
    float s = 0.f;
    for (int kk = lane; kk < D_; kk += 32)
        s = fmaf(h[(size_t)b * S_ * D_ + kk], Wcls[kk * 3 + j], s);
#pragma unroll
    for (int o = 16; o > 0; o >>= 1) s += __shfl_down_sync(0xffffffffu, s, o);
    if (lane == 0) out[j * 2 + b] = 1.f / (1.f + expf(-(s + bcls[j])));
    if (threadIdx.x < 2) out[6 + threadIdx.x] = (float)mask[(size_t)threadIdx.x * S_];
}

// ---------------- launch ----------------
extern "C" void kernel_launch(void* const* d_in, const int* in_sizes, int n_in,
                              void* d_out, int out_size) {
    const int*   src  = (const int*)d_in[0];
    const int*   mask = (const int*)d_in[1];
    const float* etok = (const float*)d_in[3];
    const float* epos = (const float*)d_in[4];
    const float* elns = (const float*)d_in[5];
    const float* elnb = (const float*)d_in[6];
    const float* Wq   = (const float*)d_in[7];   const float* bq_p  = (const float*)d_in[8];
    const float* Wk   = (const float*)d_in[9];   const float* bk_p  = (const float*)d_in[10];
    const float* Wv   = (const float*)d_in[11];  const float* bv_p  = (const float*)d_in[12];
    const float* Wo   = (const float*)d_in[13];  const float* bo_p  = (const float*)d_in[14];
    const float* Wqg  = (const float*)d_in[15];  const float* bqg_p = (const float*)d_in[16];
    const float* Wkg  = (const float*)d_in[17];  const float* bkg_p = (const float*)d_in[18];
    const float* Wvg  = (const float*)d_in[19];  const float* bvg_p = (const float*)d_in[20];
    const float* ln1s = (const float*)d_in[21];  const float* ln1b  = (const float*)d_in[22];
    const float* W1   = (const float*)d_in[23];  const float* b1_p  = (const float*)d_in[24];
    const float* W2   = (const float*)d_in[25];  const float* b2_p  = (const float*)d_in[26];
    const float* ln2s = (const float*)d_in[27];  const float* ln2b  = (const float*)d_in[28];
    const float* Wcls = (const float*)d_in[29];  const float* bcls  = (const float*)d_in[30];
    float* out = (float*)d_out;

    float *ph, *pq, *pk, *pv, *pkg, *pvg, *pa, *pt, *pf, *pqg;
    cudaGetSymbolAddress((void**)&ph,  g_h);
    cudaGetSymbolAddress((void**)&pq,  g_q);
    cudaGetSymbolAddress((void**)&pk,  g_k);
    cudaGetSymbolAddress((void**)&pv,  g_v);
    cudaGetSymbolAddress((void**)&pkg, g_kg);
    cudaGetSymbolAddress((void**)&pvg, g_vg);
    cudaGetSymbolAddress((void**)&pa,  g_a);
    cudaGetSymbolAddress((void**)&pt,  g_t);
    cudaGetSymbolAddress((void**)&pf,  g_ff);
    cudaGetSymbolAddress((void**)&pqg, g_qg);

    // allow 99KB dynamic smem on the GEMM kernels (attribute, not an allocation)
    cudaFuncSetAttribute(tgemm_kernel<0>, cudaFuncAttributeMaxDynamicSharedMemorySize, GEMM_SMEM);
    cudaFuncSetAttribute(tgemm_kernel<1>, cudaFuncAttributeMaxDynamicSharedMemorySize, GEMM_SMEM);
    cudaFuncSetAttribute(proj_gemm_kernel, cudaFuncAttributeMaxDynamicSharedMemorySize, GEMM_SMEM);

    const int M = B_ * S_;   // 4096

    embed_ln_kernel<<<M, 256>>>(src, etok, epos, elns, elnb, ph);

    for (int l = 0; l < L_; l++) {
        size_t wo  = (size_t)l * D_ * D_;
        size_t bof = (size_t)l * D_;

        ProjParams pp;
        pp.W[0] = Wq  + wo; pp.b[0] = bq_p  + bof; pp.o[0] = pq;  pp.alpha[0] = 0.125f;
        pp.W[1] = Wk  + wo; pp.b[1] = bk_p  + bof; pp.o[1] = pk;  pp.alpha[1] = 1.f;
        pp.W[2] = Wv  + wo; pp.b[2] = bv_p  + bof; pp.o[2] = pv;  pp.alpha[2] = 1.f;
        pp.W[3] = Wkg + wo; pp.b[3] = bkg_p + bof; pp.o[3] = pkg; pp.alpha[3] = 1.f;
        pp.W[4] = Wvg + wo; pp.b[4] = bvg_p + bof; pp.o[4] = pvg; pp.alpha[4] = 1.f;
        proj_gemm_kernel<<<dim3(D_ / 128, M / 128, 5), 128, GEMM_SMEM>>>(ph, pp, M, D_, D_);

        qg_kernel<<<dim3(B_, 3), 256>>>(ph, Wqg + wo, bqg_p + bof, pqg);
        attn_kernel<<<dim3(NC_, H_, B_), 256>>>(pq, pk, pv, mask, pa);
        gattn_kernel<<<dim3(H_, B_), 1024>>>(pqg, pkg, pvg, mask, pa);

        tgemm_kernel<0><<<dim3(D_ / 128, M / 128), 128, GEMM_SMEM>>>(pa, Wo + wo, bo_p + bof, pt, M, D_, D_, 1.f);
        add_ln_kernel<<<M, 256>>>(ph, pt, ln1s + bof, ln1b + bof);
        tgemm_kernel<1><<<dim3(FF_ / 128, M / 128), 128, GEMM_SMEM>>>(ph, W1 + (size_t)l * D_ * FF_,
                                                                      b1_p + (size_t)l * FF_, pf, M, FF_, D_, 1.f);
        tgemm_kernel<0><<<dim3(D_ / 128, M / 128), 128, GEMM_SMEM>>>(pf, W2 + (size_t)l * FF_ * D_,
                                                                     b2_p + bof, pt, M, D_, FF_, 1.f);
        add_ln_kernel<<<M, 256>>>(ph, pt, ln2s + bof, ln2b + bof);
    }

    cls_kernel<<<1, 192>>>(ph, Wcls, bcls, mask, out);
}

// round 15
// speedup vs baseline: 1.7180x; 1.0015x over previous
#include <cuda_runtime.h>
#include <math.h>
#include <stdint.h>

#define B_  2
#define S_  2048
#define D_  768
#define H_  12
#define HD_ 64
#define L_  4
#define FF_ 3072
#define NC_ 16
#define W_  128

// ---------------- scratch (static device arrays; no allocation) ----------------
__device__ float g_h [B_*S_*D_];
__device__ float g_q [B_*S_*D_];
__device__ float g_k [B_*S_*D_];
__device__ float g_v [B_*S_*D_];
__device__ float g_kg[B_*S_*D_];
__device__ float g_vg[B_*S_*D_];
__device__ float g_a [B_*S_*D_];
__device__ float g_t [B_*S_*D_];
__device__ float g_ff[B_*S_*FF_];
__device__ float g_qg[B_*D_];

// ---------------- helpers ----------------
__device__ __forceinline__ uint32_t smem_u32(const void* p) {
    return (uint32_t)__cvta_generic_to_shared(p);
}
__device__ __forceinline__ void cp16(uint32_t dst, const void* src) {
    asm volatile("cp.async.cg.shared.global [%0], [%1], 16;" :: "r"(dst), "l"(src));
}
__device__ __forceinline__ void cp_commit() { asm volatile("cp.async.commit_group;"); }
template <int N> __device__ __forceinline__ void cp_wait() {
    asm volatile("cp.async.wait_group %0;" :: "n"(N));
}
__device__ __forceinline__ uint32_t f2tf(float x) {
    uint32_t r;
    asm("cvt.rna.tf32.f32 %0, %1;" : "=r"(r) : "f"(x));
    return r;
}
__device__ __forceinline__ void ldsm4(uint32_t addr, unsigned* r) {
    asm volatile("ldmatrix.sync.aligned.m8n8.x4.shared.b16 {%0,%1,%2,%3}, [%4];"
        : "=r"(r[0]), "=r"(r[1]), "=r"(r[2]), "=r"(r[3]) : "r"(addr));
}

__device__ __forceinline__ void mma_tf32(float* c, const unsigned* a, const unsigned* b) {
    asm volatile(
        "mma.sync.aligned.m16n8k8.row.col.f32.tf32.tf32.f32 "
        "{%0,%1,%2,%3}, {%4,%5,%6,%7}, {%8,%9}, {%0,%1,%2,%3};"
        : "+f"(c[0]), "+f"(c[1]), "+f"(c[2]), "+f"(c[3])
        : "r"(a[0]), "r"(a[1]), "r"(a[2]), "r"(a[3]), "r"(b[0]), "r"(b[1]));
}

__device__ __forceinline__ void block_reduce2(float a, float b, float* out2) {
    __shared__ float r1[8], r2[8];
    int lane = threadIdx.x & 31, wid = threadIdx.x >> 5;
#pragma unroll
    for (int o = 16; o > 0; o >>= 1) {
        a += __shfl_down_sync(0xffffffffu, a, o);
        b += __shfl_down_sync(0xffffffffu, b, o);
    }
    if (lane == 0) { r1[wid] = a; r2[wid] = b; }
    __syncthreads();
    if (wid == 0) {
        int nw = blockDim.x >> 5;
        a = (lane < nw) ? r1[lane] : 0.f;
        b = (lane < nw) ? r2[lane] : 0.f;
#pragma unroll
        for (int o = 4; o > 0; o >>= 1) {
            a += __shfl_down_sync(0xffffffffu, a, o);
            b += __shfl_down_sync(0xffffffffu, b, o);
        }
        if (lane == 0) { out2[0] = a; out2[1] = b; }
    }
    __syncthreads();
}

// ---------------- tf32 GEMM: BK=32, 3-stage cp.async, fragment double-buffer ----
// C = act((A@B + bias) * alpha); A: MxK rm, B: KxN rm. M%128==N%128==K%32==0.
// Block 128x128x32, 128 thr, 4 warps 2x2 (warp tile 64x64).
// A stage: 128 rows x 32 words (128B rows), chunk swizzle c^(row&7). B stage:
// 32 rows x 136 words. Fragments for ks+1 load while MMAs of ks issue.
#define GEMM_ASTG (128 * 32)
#define GEMM_BSTG (32 * 136)
#define GEMM_SMEM (3 * (GEMM_ASTG + GEMM_BSTG) * 4)

template <int ACT>
__device__ __forceinline__ void gemm_core(
    const float* __restrict__ A, const float* __restrict__ Bm,
    const float* __restrict__ bias, float* __restrict__ C,
    int M, int N, int K, float alpha) {
    extern __shared__ uint32_t dyn[];
    uint32_t* As = dyn;
    uint32_t* Bs = dyn + 3 * GEMM_ASTG;

    const int tid = threadIdx.x, lane = tid & 31, wid = tid >> 5;
    const int wm = (wid >> 1) * 64, wn = (wid & 1) * 64;
    const int g = lane >> 2, t = lane & 3;
    const int bm = blockIdx.y * 128, bn = blockIdx.x * 128;

    const float* aP = A + (size_t)(bm + (tid >> 3)) * K + (tid & 7) * 4;
    const float* bP = Bm + (size_t)(tid >> 5) * N + bn + (tid & 31) * 4;
    const uint32_t aD0 = smem_u32(As) + ((tid >> 3) << 7)
                       + ((((tid & 7) ^ ((tid >> 3) & 7))) << 4);
    const uint32_t bD0 = smem_u32(Bs) + (((tid >> 5) * 136 + (tid & 31) * 4) << 2);

    const int lm = lane >> 3, lr = lane & 7;
    const uint32_t aLd = smem_u32(As) + ((wm + (lm & 1) * 8 + lr) << 7);
    const int csel = lm >> 1;

    float acc[4][8][4];
#pragma unroll
    for (int i = 0; i < 4; i++)
#pragma unroll
        for (int j = 0; j < 8; j++)
#pragma unroll
            for (int r = 0; r < 4; r++) acc[i][j][r] = 0.f;

    const int nk = K >> 5;

    auto issue = [&](int kt) {
        const int s = kt % 3;
        const int k0 = kt << 5;
        const float* ap = aP + k0;
        const float* bp = bP + (size_t)k0 * N;
        const uint32_t ad = aD0 + s * (GEMM_ASTG * 4);
        const uint32_t bd = bD0 + s * (GEMM_BSTG * 4);
#pragma unroll
        for (int i = 0; i < 8; i++) {
            cp16(ad + i * 2048, ap + (size_t)(i * 16) * K);
            cp16(bd + i * 2176, bp + (size_t)(i * 4) * N);
        }
        cp_commit();
    };

    issue(0);
    if (nk > 1) issue(1);

    for (int kt = 0; kt < nk; kt++) {
        if (kt + 1 == nk) cp_wait<0>(); else cp_wait<1>();
        __syncthreads();
        if (kt + 2 < nk) issue(kt + 2);

        const uint32_t sa = aLd + (kt % 3) * (GEMM_ASTG * 4);
        const uint32_t* sB = &Bs[(kt % 3) * GEMM_BSTG];

        unsigned af[2][4][4], bf[2][8][2];

        auto loadfrag = [&](int ks, int buf) {
            const int kb = ks * 8;
            const uint32_t aoff = (uint32_t)((((2 * ks + csel) ^ lr) & 7) << 4);
#pragma unroll
            for (int mt = 0; mt < 4; mt++)
                ldsm4(sa + mt * 2048 + aoff, af[buf][mt]);
#pragma unroll
            for (int nt = 0; nt < 8; nt++) {
                int cc = wn + nt * 8 + g;
                bf[buf][nt][0] = sB[(kb + t) * 136 + cc];
                bf[buf][nt][1] = sB[(kb + t + 4) * 136 + cc];
            }
        };

        loadfrag(0, 0);
#pragma unroll
        for (int ks = 0; ks < 4; ks++) {
            const int cur = ks & 1;
            if (ks < 3) loadfrag(ks + 1, cur ^ 1);
#pragma unroll
            for (int mt = 0; mt < 4; mt++)
#pragma unroll
                for (int nt = 0; nt < 8; nt++)
                    mma_tf32(acc[mt][nt], af[cur][mt], bf[cur][nt]);
        }
        __syncthreads();
    }

    // epilogue
#pragma unroll
    for (int mt = 0; mt < 4; mt++) {
#pragma unroll
        for (int nt = 0; nt < 8; nt++) {
            int r0 = bm + wm + mt * 16 + g;
            int c0 = bn + wn + nt * 8 + t * 2;
            float b0 = bias[c0], b1 = bias[c0 + 1];
            float v[4];
            v[0] = (acc[mt][nt][0] + b0) * alpha;
            v[1] = (acc[mt][nt][1] + b1) * alpha;
            v[2] = (acc[mt][nt][2] + b0) * alpha;
            v[3] = (acc[mt][nt][3] + b1) * alpha;
            if (ACT == 1) {
#pragma unroll
                for (int i = 0; i < 4; i++)
                    v[i] = 0.5f * v[i] * (1.f + erff(v[i] * 0.7071067811865476f));
            }
            *(float2*)(C + (size_t)r0 * N + c0)       = make_float2(v[0], v[1]);
            *(float2*)(C + (size_t)(r0 + 8) * N + c0) = make_float2(v[2], v[3]);
        }
    }
}

template <int ACT>
__global__ void __launch_bounds__(128, 2) tgemm_kernel(
    const float* __restrict__ A, const float* __restrict__ Bm,
    const float* __restrict__ bias, float* __restrict__ C,
    int M, int N, int K, float alpha) {
    gemm_core<ACT>(A, Bm, bias, C, M, N, K, alpha);
}

struct ProjParams {
    const float* W[5];
    const float* b[5];
    float*       o[5];
    float        alpha[5];
};

__global__ void __launch_bounds__(128, 2) proj_gemm_kernel(
    const float* __restrict__ A, ProjParams p, int M, int N, int K) {
    int z = blockIdx.z;
    gemm_core<0>(A, p.W[z], p.b[z], p.o[z], M, N, K, p.alpha[z]);
}

// ---------------- embedding + LN ----------------
__global__ void embed_ln_kernel(const int* __restrict__ src,
                                const float* __restrict__ etok,
                                const float* __restrict__ epos,
                                const float* __restrict__ gs,
                                const float* __restrict__ gb,
                                float* __restrict__ h) {
    int tok = blockIdx.x;
    int s   = tok & (S_ - 1);
    int tid = threadIdx.x;
    __shared__ float stat[2];
    size_t row = (size_t)src[tok] * D_;
    float vals[3]; float sum = 0.f, sq = 0.f;
#pragma unroll
    for (int i = 0; i < 3; i++) {
        int d = tid + i * 256;
        float v = etok[row + d] + epos[(size_t)s * D_ + d];
        vals[i] = v; sum += v; sq += v * v;
    }
    block_reduce2(sum, sq, stat);
    float mean = stat[0] * (1.f / D_);
    float var  = stat[1] * (1.f / D_) - mean * mean;
    float inv  = 1.f / sqrtf(var + 1e-5f);
#pragma unroll
    for (int i = 0; i < 3; i++) {
        int d = tid + i * 256;
        h[(size_t)tok * D_ + d] = (vals[i] - mean) * inv * gs[d] + gb[d];
    }
}

// ---------------- residual add + LN (in place on h) ----------------
__global__ void add_ln_kernel(float* __restrict__ h, const float* __restrict__ x,
                              const float* __restrict__ sc, const float* __restrict__ bi) {
    int tok = blockIdx.x;
    int tid = threadIdx.x;
    __shared__ float stat[2];
    float* hp = h + (size_t)tok * D_;
    const float* xp = x + (size_t)tok * D_;
    float vals[3]; float sum = 0.f, sq = 0.f;
#pragma unroll
    for (int i = 0; i < 3; i++) {
        int d = tid + i * 256;
        float v = hp[d] + xp[d];
        vals[i] = v; sum += v; sq += v * v;
    }
    block_reduce2(sum, sq, stat);
    float mean = stat[0] * (1.f / D_);
    float var  = stat[1] * (1.f / D_) - mean * mean;
    float inv  = 1.f / sqrtf(var + 1e-5f);
#pragma unroll
    for (int i = 0; i < 3; i++) {
        int d = tid + i * 256;
        hp[d] = (vals[i] - mean) * inv * sc[d] + bi[d];
    }
}

// ---------------- qg = (h[:,0,:] @ Wqg + bqg) / 8 ----------------
__global__ void qg_kernel(const float* __restrict__ h, const float* __restrict__ Wm,
                          const float* __restrict__ bias, float* __restrict__ qg) {
    int b = blockIdx.x;
    int j = blockIdx.y * 256 + threadIdx.x;
    __shared__ float hs[D_];
    for (int i = threadIdx.x; i < D_; i += 256) hs[i] = h[(size_t)b * S_ * D_ + i];
    __syncthreads();
    float s = 0.f;
    for (int kk = 0; kk < D_; kk++) s = fmaf(hs[kk], Wm[(size_t)kk * D_ + j], s);
    qg[b * D_ + j] = (s + bias[j]) * 0.125f;
}

// ---------------- sliding-window + global-key attention (tensor-core flash) -----
__global__ void __launch_bounds__(256) attn_kernel(
    const float* __restrict__ q, const float* __restrict__ k, const float* __restrict__ v,
    const int* __restrict__ mask, float* __restrict__ out) {
    const int c = blockIdx.x, hh = blockIdx.y, b = blockIdx.z;
    const int tid = threadIdx.x, lane = tid & 31, wid = tid >> 5;
    const int g = lane >> 2, t = lane & 3;
    const int wq = wid * 16;
    __shared__ float Ks[64 * 68];
    __shared__ float Vs[64 * 72];
    __shared__ float k0s[64], v0s[64];
    __shared__ int vld[64];

    const size_t hb = (size_t)b * S_ * D_ + hh * HD_;

    if (tid < 64) { k0s[tid] = k[hb + tid]; v0s[tid] = v[hb + tid]; }

    uint32_t Qf[8][4];
    {
        const float* qr0 = q + hb + (size_t)(c * W_ + wq + g) * D_;
        const float* qr1 = qr0 + 8 * D_;
#pragma unroll
        for (int kk = 0; kk < 8; kk++) {
            Qf[kk][0] = f2tf(qr0[kk * 8 + t]);
            Qf[kk][1] = f2tf(qr1[kk * 8 + t]);
            Qf[kk][2] = f2tf(qr0[kk * 8 + t + 4]);
            Qf[kk][3] = f2tf(qr1[kk * 8 + t + 4]);
        }
    }
    __syncthreads();

    float p0 = 0.f, p1 = 0.f;
#pragma unroll
    for (int kk = 0; kk < 8; kk++) {
        p0 += __uint_as_float(Qf[kk][0]) * k0s[kk*8 + t] + __uint_as_float(Qf[kk][2]) * k0s[kk*8 + t + 4];
        p1 += __uint_as_float(Qf[kk][1]) * k0s[kk*8 + t] + __uint_as_float(Qf[kk][3]) * k0s[kk*8 + t + 4];
    }
    p0 += __shfl_xor_sync(0xffffffffu, p0, 1); p0 += __shfl_xor_sync(0xffffffffu, p0, 2);
    p1 += __shfl_xor_sync(0xffffffffu, p1, 1); p1 += __shfl_xor_sync(0xffffffffu, p1, 2);

    const bool m0set = mask[(size_t)b * S_] != 0;
    float m0 = m0set ? p0 : -1e30f;
    float m1 = m0set ? p1 : -1e30f;
    float l0 = m0set ? 1.f : 0.f;
    float l1 = l0;
    float acc[8][4];
#pragma unroll
    for (int nt = 0; nt < 8; nt++) {
        float va = m0set ? v0s[nt*8 + 2*t]     : 0.f;
        float vb = m0set ? v0s[nt*8 + 2*t + 1] : 0.f;
        acc[nt][0] = va; acc[nt][1] = vb; acc[nt][2] = va; acc[nt][3] = vb;
    }

    const int base = c * W_ - W_;
    const int q0r = wq + g, q1r = q0r + 8;
    const uint32_t* Ku = (const uint32_t*)Ks;
    const uint32_t* Vu = (const uint32_t*)Vs;

    for (int tile = 0; tile < 6; tile++) {
        __syncthreads();
#pragma unroll
        for (int e = 0; e < 4; e++) {
            int id = tid + e * 256;
            int r = id >> 4, c4 = (id & 15) * 4;
            int p = base + tile * 64 + r;
            float4 kv = make_float4(0.f,0.f,0.f,0.f), vv = kv;
            if (p >= 0 && p < S_) {
                size_t off = hb + (size_t)p * D_ + c4;
                kv = *(const float4*)(k + off);
                vv = *(const float4*)(v + off);
            }
            uint32_t* kd = (uint32_t*)&Ks[r * 68 + c4];
            kd[0] = f2tf(kv.x); kd[1] = f2tf(kv.y); kd[2] = f2tf(kv.z); kd[3] = f2tf(kv.w);
            uint32_t* vd = (uint32_t*)&Vs[r * 72 + c4];
            vd[0] = f2tf(vv.x); vd[1] = f2tf(vv.y); vd[2] = f2tf(vv.z); vd[3] = f2tf(vv.w);
        }
        if (tid < 64) {
            int p = base + tile * 64 + tid;
            vld[tid] = (p >= 0 && p < S_) ? (mask[(size_t)b * S_ + p] != 0) : 0;
        }
        __syncthreads();

        float sc[8][4];
#pragma unroll
        for (int nt = 0; nt < 8; nt++) { sc[nt][0]=0.f; sc[nt][1]=0.f; sc[nt][2]=0.f; sc[nt][3]=0.f; }
#pragma unroll
        for (int kk = 0; kk < 8; kk++) {
#pragma unroll
            for (int nt = 0; nt < 8; nt++) {
                unsigned bf[2];
                bf[0] = Ku[(nt*8 + g) * 68 + kk*8 + t];
                bf[1] = Ku[(nt*8 + g) * 68 + kk*8 + t + 4];
                mma_tf32(sc[nt], Qf[kk], bf);
            }
        }

        float tm0 = -1e30f, tm1 = -1e30f;
#pragma unroll
        for (int nt = 0; nt < 8; nt++) {
            int j0 = tile*64 + nt*8 + 2*t, j1 = j0 + 1;
            bool ok00 = (j0 >= q0r) && (j0 <= q0r + 2*W_) && vld[nt*8 + 2*t];
            bool ok01 = (j1 >= q0r) && (j1 <= q0r + 2*W_) && vld[nt*8 + 2*t + 1];
            bool ok10 = (j0 >= q1r) && (j0 <= q1r + 2*W_) && vld[nt*8 + 2*t];
            bool ok11 = (j1 >= q1r) && (j1 <= q1r + 2*W_) && vld[nt*8 + 2*t + 1];
            sc[nt][0] = ok00 ? sc[nt][0] : -1e30f;
            sc[nt][1] = ok01 ? sc[nt][1] : -1e30f;
            sc[nt][2] = ok10 ? sc[nt][2] : -1e30f;
            sc[nt][3] = ok11 ? sc[nt][3] : -1e30f;
            tm0 = fmaxf(tm0, fmaxf(sc[nt][0], sc[nt][1]));
            tm1 = fmaxf(tm1, fmaxf(sc[nt][2], sc[nt][3]));
        }
        tm0 = fmaxf(tm0, __shfl_xor_sync(0xffffffffu, tm0, 1));
        tm0 = fmaxf(tm0, __shfl_xor_sync(0xffffffffu, tm0, 2));
        tm1 = fmaxf(tm1, __shfl_xor_sync(0xffffffffu, tm1, 1));
        tm1 = fmaxf(tm1, __shfl_xor_sync(0xffffffffu, tm1, 2));

        float nm0 = fmaxf(m0, tm0), nm1 = fmaxf(m1, tm1);
        float cr0 = __expf(m0 - nm0), cr1 = __expf(m1 - nm1);
        m0 = nm0; m1 = nm1; l0 *= cr0; l1 *= cr1;

        float ps0 = 0.f, ps1 = 0.f;
#pragma unroll
        for (int nt = 0; nt < 8; nt++) {
            sc[nt][0] = (sc[nt][0] > -1e29f) ? __expf(sc[nt][0] - m0) : 0.f;
            sc[nt][1] = (sc[nt][1] > -1e29f) ? __expf(sc[nt][1] - m0) : 0.f;
            sc[nt][2] = (sc[nt][2] > -1e29f) ? __expf(sc[nt][2] - m1) : 0.f;
            sc[nt][3] = (sc[nt][3] > -1e29f) ? __expf(sc[nt][3] - m1) : 0.f;
            ps0 += sc[nt][0] + sc[nt][1];
            ps1 += sc[nt][2] + sc[nt][3];
            acc[nt][0] *= cr0; acc[nt][1] *= cr0; acc[nt][2] *= cr1; acc[nt][3] *= cr1;
        }
        ps0 += __shfl_xor_sync(0xffffffffu, ps0, 1); ps0 += __shfl_xor_sync(0xffffffffu, ps0, 2);
        ps1 += __shfl_xor_sync(0xffffffffu, ps1, 1); ps1 += __shfl_xor_sync(0xffffffffu, ps1, 2);
        l0 += ps0; l1 += ps1;

        const int src0 = (lane & ~3) | (t >> 1);
        const int src1 = src0 + 2;
        const bool odd = t & 1;
#pragma unroll
        for (int kk = 0; kk < 8; kk++) {
            float x0 = __shfl_sync(0xffffffffu, sc[kk][0], src0);
            float x1 = __shfl_sync(0xffffffffu, sc[kk][1], src0);
            float x2 = __shfl_sync(0xffffffffu, sc[kk][2], src0);
            float x3 = __shfl_sync(0xffffffffu, sc[kk][3], src0);
            float y0 = __shfl_sync(0xffffffffu, sc[kk][0], src1);
            float y1 = __shfl_sync(0xffffffffu, sc[kk][1], src1);
            float y2 = __shfl_sync(0xffffffffu, sc[kk][2], src1);
            float y3 = __shfl_sync(0xffffffffu, sc[kk][3], src1);
            unsigned af[4];
            af[0] = f2tf(odd ? x1 : x0);
            af[1] = f2tf(odd ? x3 : x2);
            af[2] = f2tf(odd ? y1 : y0);
            af[3] = f2tf(odd ? y3 : y2);
#pragma unroll
            for (int nt = 0; nt < 8; nt++) {
                unsigned bf[2];
                bf[0] = Vu[(kk*8 + t) * 72 + nt*8 + g];
                bf[1] = Vu[(kk*8 + t + 4) * 72 + nt*8 + g];
                mma_tf32(acc[nt], af, bf);
            }
        }
    }

    float inv0 = 1.f / l0, inv1 = 1.f / l1;
    float* or0 = out + hb + (size_t)(c * W_ + wq + g) * D_;
    float* or1 = or0 + 8 * D_;
#pragma unroll
    for (int nt = 0; nt < 8; nt++) {
        *(float2*)(or0 + nt*8 + 2*t) = make_float2(acc[nt][0] * inv0, acc[nt][1] * inv0);
        *(float2*)(or1 + nt*8 + 2*t) = make_float2(acc[nt][2] * inv1, acc[nt][3] * inv1);
    }
}

// ---------------- global-token attention -> overwrite out row 0 (1024 thr) ------
__global__ void __launch_bounds__(1024) gattn_kernel(
    const float* __restrict__ qg, const float* __restrict__ kg,
    const float* __restrict__ vg, const int* __restrict__ mask,
    float* __restrict__ out) {
    const int hh = blockIdx.x, b = blockIdx.y;
    const int tid = threadIdx.x;
    const int lane = tid & 31, wrp = tid >> 5;
    __shared__ float sc[S_];
    __shared__ float qs[HD_];
    __shared__ float r1[32];
    __shared__ float stat[2];
    __shared__ float accb[16][HD_];
    if (tid < HD_) qs[tid] = qg[b * D_ + hh * HD_ + tid];
    __syncthreads();
    float lmax = -3.4e38f;
    for (int s = tid; s < S_; s += 1024) {
        const float4* kr = (const float4*)(kg + ((size_t)b * S_ + s) * D_ + hh * HD_);
        float dot = 0.f;
#pragma unroll
        for (int i = 0; i < 16; i++) {
            float4 k4 = kr[i];
            dot = fmaf(qs[i*4], k4.x, dot);   dot = fmaf(qs[i*4+1], k4.y, dot);
            dot = fmaf(qs[i*4+2], k4.z, dot); dot = fmaf(qs[i*4+3], k4.w, dot);
        }
        if (mask[(size_t)b * S_ + s] == 0) dot = -1e9f;
        sc[s] = dot;
        lmax = fmaxf(lmax, dot);
    }
#pragma unroll
    for (int o = 16; o > 0; o >>= 1) lmax = fmaxf(lmax, __shfl_down_sync(0xffffffffu, lmax, o));
    if (lane == 0) r1[wrp] = lmax;
    __syncthreads();
    if (wrp == 0) {
        float m2 = r1[lane];
#pragma unroll
        for (int o = 16; o > 0; o >>= 1) m2 = fmaxf(m2, __shfl_down_sync(0xffffffffu, m2, o));
        if (lane == 0) stat[0] = m2;
    }
    __syncthreads();
    float gmax = stat[0];
    float lsum = 0.f;
    for (int s = tid; s < S_; s += 1024) {
        float e = __expf(sc[s] - gmax);
        sc[s] = e;
        lsum += e;
    }
#pragma unroll
    for (int o = 16; o > 0; o >>= 1) lsum += __shfl_down_sync(0xffffffffu, lsum, o);
    if (lane == 0) r1[wrp] = lsum;
    __syncthreads();
    if (wrp == 0) {
        float s2 = r1[lane];
#pragma unroll
        for (int o = 16; o > 0; o >>= 1) s2 += __shfl_down_sync(0xffffffffu, s2, o);
        if (lane == 0) stat[1] = s2;
    }
    __syncthreads();
    float inv = 1.f / stat[1];
    int d = tid & 63, part = tid >> 6;
    float a = 0.f;
    for (int s = part; s < S_; s += 16)
        a = fmaf(sc[s], vg[((size_t)b * S_ + s) * D_ + hh * HD_ + d], a);
    accb[part][d] = a;
    __syncthreads();
    if (tid < HD_) {
        float r = 0.f;
#pragma unroll
        for (int p = 0; p < 16; p++) r += accb[p][tid];
        out[(size_t)b * S_ * D_ + hh * HD_ + tid] = r * inv;
    }
}

// ---------------- classifier head ----------------
__global__ void cls_kernel(const float* __restrict__ h, const float* __restrict__ Wcls,
                           const float* __restrict__ bcls, const int* __restrict__ mask,
                           float* __restrict__ out) {
    int w = threadIdx.x >> 5, lane = threadIdx.x & 31;
    int b = w & 1, j = w >> 1;
    float s = 0.f;
    for (int kk = lane; kk < D_; kk += 32)
        s = fmaf(h[(size_t)b * S_ * D_ + kk], Wcls[kk * 3 + j], s);
#pragma unroll
    for (int o = 16; o > 0; o >>= 1) s += __shfl_down_sync(0xffffffffu, s, o);
    if (lane == 0) out[j * 2 + b] = 1.f / (1.f + expf(-(s + bcls[j])));
    if (threadIdx.x < 2) out[6 + threadIdx.x] = (float)mask[(size_t)threadIdx.x * S_];
}

// ---------------- launch ----------------
extern "C" void kernel_launch(void* const* d_in, const int* in_sizes, int n_in,
                              void* d_out, int out_size) {
    const int*   src  = (const int*)d_in[0];
    const int*   mask = (const int*)d_in[1];
    const float* etok = (const float*)d_in[3];
    const float* epos = (const float*)d_in[4];
    const float* elns = (const float*)d_in[5];
    const float* elnb = (const float*)d_in[6];
    const float* Wq   = (const float*)d_in[7];   const float* bq_p  = (const float*)d_in[8];
    const float* Wk   = (const float*)d_in[9];   const float* bk_p  = (const float*)d_in[10];
    const float* Wv   = (const float*)d_in[11];  const float* bv_p  = (const float*)d_in[12];
    const float* Wo   = (const float*)d_in[13];  const float* bo_p  = (const float*)d_in[14];
    const float* Wqg  = (const float*)d_in[15];  const float* bqg_p = (const float*)d_in[16];
    const float* Wkg  = (const float*)d_in[17];  const float* bkg_p = (const float*)d_in[18];
    const float* Wvg  = (const float*)d_in[19];  const float* bvg_p = (const float*)d_in[20];
    const float* ln1s = (const float*)d_in[21];  const float* ln1b  = (const float*)d_in[22];
    const float* W1   = (const float*)d_in[23];  const float* b1_p  = (const float*)d_in[24];
    const float* W2   = (const float*)d_in[25];  const float* b2_p  = (const float*)d_in[26];
    const float* ln2s = (const float*)d_in[27];  const float* ln2b  = (const float*)d_in[28];
    const float* Wcls = (const float*)d_in[29];  const float* bcls  = (const float*)d_in[30];
    float* out = (float*)d_out;

    float *ph, *pq, *pk, *pv, *pkg, *pvg, *pa, *pt, *pf, *pqg;
    cudaGetSymbolAddress((void**)&ph,  g_h);
    cudaGetSymbolAddress((void**)&pq,  g_q);
    cudaGetSymbolAddress((void**)&pk,  g_k);
    cudaGetSymbolAddress((void**)&pv,  g_v);
    cudaGetSymbolAddress((void**)&pkg, g_kg);
    cudaGetSymbolAddress((void**)&pvg, g_vg);
    cudaGetSymbolAddress((void**)&pa,  g_a);
    cudaGetSymbolAddress((void**)&pt,  g_t);
    cudaGetSymbolAddress((void**)&pf,  g_ff);
    cudaGetSymbolAddress((void**)&pqg, g_qg);

    cudaFuncSetAttribute(tgemm_kernel<0>, cudaFuncAttributeMaxDynamicSharedMemorySize, GEMM_SMEM);
    cudaFuncSetAttribute(tgemm_kernel<1>, cudaFuncAttributeMaxDynamicSharedMemorySize, GEMM_SMEM);
    cudaFuncSetAttribute(proj_gemm_kernel, cudaFuncAttributeMaxDynamicSharedMemorySize, GEMM_SMEM);

    const int M = B_ * S_;   // 4096

    embed_ln_kernel<<<M, 256>>>(src, etok, epos, elns, elnb, ph);

    for (int l = 0; l < L_; l++) {
        size_t wo  = (size_t)l * D_ * D_;
        size_t bof = (size_t)l * D_;

        ProjParams pp;
        pp.W[0] = Wq  + wo; pp.b[0] = bq_p  + bof; pp.o[0] = pq;  pp.alpha[0] = 0.125f;
        pp.W[1] = Wk  + wo; pp.b[1] = bk_p  + bof; pp.o[1] = pk;  pp.alpha[1] = 1.f;
        pp.W[2] = Wv  + wo; pp.b[2] = bv_p  + bof; pp.o[2] = pv;  pp.alpha[2] = 1.f;
        pp.W[3] = Wkg + wo; pp.b[3] = bkg_p + bof; pp.o[3] = pkg; pp.alpha[3] = 1.f;
        pp.W[4] = Wvg + wo; pp.b[4] = bvg_p + bof; pp.o[4] = pvg; pp.alpha[4] = 1.f;
        proj_gemm_kernel<<<dim3(D_ / 128, M / 128, 5), 128, GEMM_SMEM>>>(ph, pp, M, D_, D_);

        qg_kernel<<<dim3(B_, 3), 256>>>(ph, Wqg + wo, bqg_p + bof, pqg);
        attn_kernel<<<dim3(NC_, H_, B_), 256>>>(pq, pk, pv, mask, pa);
        gattn_kernel<<<dim3(H_, B_), 1024>>>(pqg, pkg, pvg, mask, pa);

        tgemm_kernel<0><<<dim3(D_ / 128, M / 128), 128, GEMM_SMEM>>>(pa, Wo + wo, bo_p + bof, pt, M, D_, D_, 1.f);
        add_ln_kernel<<<M, 256>>>(ph, pt, ln1s + bof, ln1b + bof);
        tgemm_kernel<1><<<dim3(FF_ / 128, M / 128), 128, GEMM_SMEM>>>(ph, W1 + (size_t)l * D_ * FF_,
                                                                      b1_p + (size_t)l * FF_, pf, M, FF_, D_, 1.f);
        tgemm_kernel<0><<<dim3(D_ / 128, M / 128), 128, GEMM_SMEM>>>(pf, W2 + (size_t)l * FF_ * D_,
                                                                     b2_p + bof, pt, M, D_, FF_, 1.f);
        add_ln_kernel<<<M, 256>>>(ph, pt, ln2s + bof, ln2b + bof);
    }

    cls_kernel<<<1, 192>>>(ph, Wcls, bcls, mask, out);
}